// round 2
// baseline (speedup 1.0000x reference)
#include <cuda_runtime.h>
#include <cstdint>

#define BB 2
#define SS 2048
#define DM 1024
#define HH 8
#define HD 64
#define NREL 8
#define MTOT (BB*SS)          // 4096 rows (b,s flattened)
#define PLD 3584              // fused projection row stride (7*512)

// ---------------- scratch (device globals; no allocation allowed) ----------------
static __device__ float g_wcat[(size_t)7*512*DM];                 // 14 MB
static __device__ float g_proj[(size_t)MTOT*PLD];                 // 59 MB
static __device__ float g_sv[(size_t)MTOT*512];                   // 8.4 MB
static __device__ float g_sc_sa[(size_t)BB*HH*SS*SS];             // 268 MB (scores -> alpha in place)
static __device__ float g_sc_ra[(size_t)BB*HH*SS*SS];             // 268 MB
static __device__ float g_rel[(size_t)BB*NREL*SS*SS];             // 268 MB
static __device__ float g_ctx_sa[(size_t)MTOT*512];               // 8.4 MB
static __device__ float g_ctx_ra[(size_t)MTOT*512];               // 8.4 MB
static __device__ float g_attrel[(size_t)MTOT*64];                // 1 MB

// ==================================================================================
// Tensor-core 3xTF32 GEMM.
//   C = scale * A(M,K) * op(B), fp32 in/out, internally split x = hi + lo (tf32)
//   D += Ah*Bh + Ah*Bl + Al*Bh  (error ~1e-6 rel, vs ~4e-4 for single tf32)
// Tile: BM=128 x BN_(128|64) x BK=16. 256 threads = 8 warps in a 2x4 grid,
// warptile 64 x (BN_/4). Smem holds fragment-ordered tf32 so each lane's A-frag
// is one LDS.128 and B-frag one LDS.64.
// TRANSB=true : B is (N,K) row-major.  TRANSB=false: B is (K,N) row-major.
// CAUSAL: skip blocks fully above diagonal (BM==BN). KCLAMP: K limited to m0+BM.
// All problem dims here are multiples of the tile dims (no bounds checks).
// ==================================================================================
#define BM 128
#define BKT 16

__device__ __forceinline__ void tf32_split(float x, uint32_t& h, uint32_t& l) {
    uint32_t hb;
    asm("cvt.rna.tf32.f32 %0, %1;" : "=r"(hb) : "f"(x));
    float lf = x - __uint_as_float(hb);
    uint32_t lb;
    asm("cvt.rna.tf32.f32 %0, %1;" : "=r"(lb) : "f"(lf));
    h = hb; l = lb;
}

__device__ __forceinline__ void mma_tf32(float* c, const uint32_t* a, const uint32_t* b) {
    asm volatile(
        "mma.sync.aligned.m16n8k8.row.col.f32.tf32.tf32.f32 "
        "{%0,%1,%2,%3}, {%4,%5,%6,%7}, {%8,%9}, {%0,%1,%2,%3};\n"
        : "+f"(c[0]), "+f"(c[1]), "+f"(c[2]), "+f"(c[3])
        : "r"(a[0]), "r"(a[1]), "r"(a[2]), "r"(a[3]), "r"(b[0]), "r"(b[1]));
}

template<int BN_, bool TRANSB, bool CAUSAL, bool KCLAMP>
__global__ __launch_bounds__(256)
void gemm_tc(const float* __restrict__ A, int lda, long long sAo, long long sAi,
             const float* __restrict__ B, int ldb, long long sBo, long long sBi,
             float* __restrict__ C, int ldc, long long sCo, long long sCi,
             int M, int N, int K, int inner, float scale)
{
    constexpr int NT8 = BN_ / 8;            // 8x8 B tiles across BN_
    constexpr int NW  = NT8 / 4;            // B tiles per warp (4 warp cols)
    constexpr int ALD = 2;                  // A float4 loads / thread
    constexpr int BLD = (BN_ * BKT) / (4 * 256); // B float4 loads / thread (2 or 1)

    int bx = blockIdx.x, by = blockIdx.y, bz = blockIdx.z;
    if (CAUSAL && bx > by) return;
    int outer = bz / inner, in = bz % inner;
    A += outer * sAo + (long long)in * sAi;
    B += outer * sBo + (long long)in * sBi;
    C += outer * sCo + (long long)in * sCi;
    int m0 = by * BM, n0 = bx * BN_;
    int kend = K;
    if (KCLAMP) kend = min(K, m0 + BM);
    int ktiles = kend >> 4;

    // fragment-ordered smem: [hi/lo][k8][tile][lane][reg]
    __shared__ __align__(16) uint32_t sA[2][2][8][32][4];     // 16 KB
    __shared__ __align__(16) uint32_t sB[2][2][NT8][32][2];   // 16|8 KB

    int tid = threadIdx.x;
    int wid = tid >> 5, lane = tid & 31;
    int wm = wid >> 2, wn = wid & 3;

    float c[4][NW][4];
#pragma unroll
    for (int i = 0; i < 4; i++)
#pragma unroll
        for (int j = 0; j < NW; j++)
#pragma unroll
            for (int r = 0; r < 4; r++) c[i][j][r] = 0.f;

    float4 rA[ALD], rB[BLD];

    // ---- global -> register loads for k-tile kt
    auto g2r = [&](int kt) {
        int k0 = kt << 4;
#pragma unroll
        for (int it = 0; it < ALD; it++) {
            int idx = tid + it * 256;
            int row = idx >> 2, kq = (idx & 3) << 2;
            rA[it] = *(const float4*)(A + (size_t)(m0 + row) * lda + k0 + kq);
        }
        if (TRANSB) {
#pragma unroll
            for (int it = 0; it < BLD; it++) {
                int idx = tid + it * 256;
                int n = idx >> 2, kq = (idx & 3) << 2;
                rB[it] = *(const float4*)(B + (size_t)(n0 + n) * ldb + k0 + kq);
            }
        } else {
#pragma unroll
            for (int it = 0; it < BLD; it++) {
                int idx = tid + it * 256;
                int krow = idx / (BN_ / 4), nq = (idx % (BN_ / 4)) << 2;
                rB[it] = *(const float4*)(B + (size_t)(k0 + krow) * ldb + n0 + nq);
            }
        }
    };

    // ---- register -> smem (with hi/lo split into fragment order)
    auto sts = [&]() {
#pragma unroll
        for (int it = 0; it < ALD; it++) {
            int idx = tid + it * 256;
            int row = idx >> 2, kq = (idx & 3) << 2;
            float v[4] = {rA[it].x, rA[it].y, rA[it].z, rA[it].w};
#pragma unroll
            for (int e = 0; e < 4; e++) {
                int k = kq + e, k8 = k >> 3, kk = k & 7;
                int mt = row >> 4;
                int ln = ((row & 7) << 2) | (kk & 3);
                int rg = ((row >> 3) & 1) | ((kk >> 2) << 1);
                uint32_t h, l; tf32_split(v[e], h, l);
                sA[0][k8][mt][ln][rg] = h;
                sA[1][k8][mt][ln][rg] = l;
            }
        }
#pragma unroll
        for (int it = 0; it < BLD; it++) {
            int idx = tid + it * 256;
            float v[4] = {rB[it].x, rB[it].y, rB[it].z, rB[it].w};
#pragma unroll
            for (int e = 0; e < 4; e++) {
                int n, k;
                if (TRANSB) { n = idx >> 2; k = ((idx & 3) << 2) + e; }
                else        { k = idx / (BN_ / 4); n = ((idx % (BN_ / 4)) << 2) + e; }
                int k8 = k >> 3, kk = k & 7;
                int n8 = n >> 3;
                int ln = ((n & 7) << 2) | (kk & 3);
                int rg = (kk >> 2) & 1;
                uint32_t h, l; tf32_split(v[e], h, l);
                sB[0][k8][n8][ln][rg] = h;
                sB[1][k8][n8][ln][rg] = l;
            }
        }
    };

    g2r(0);
    for (int kt = 0; kt < ktiles; kt++) {
        sts();
        __syncthreads();
        if (kt + 1 < ktiles) g2r(kt + 1);

#pragma unroll
        for (int k8 = 0; k8 < 2; k8++) {
            uint32_t ah[4][4], al[4][4], bh[NW][2], bl[NW][2];
#pragma unroll
            for (int i = 0; i < 4; i++) {
                *(uint4*)ah[i] = *(const uint4*)&sA[0][k8][wm * 4 + i][lane][0];
                *(uint4*)al[i] = *(const uint4*)&sA[1][k8][wm * 4 + i][lane][0];
            }
#pragma unroll
            for (int j = 0; j < NW; j++) {
                *(uint2*)bh[j] = *(const uint2*)&sB[0][k8][wn * NW + j][lane][0];
                *(uint2*)bl[j] = *(const uint2*)&sB[1][k8][wn * NW + j][lane][0];
            }
#pragma unroll
            for (int i = 0; i < 4; i++)
#pragma unroll
                for (int j = 0; j < NW; j++) {
                    mma_tf32(c[i][j], ah[i], bh[j]);
                    mma_tf32(c[i][j], ah[i], bl[j]);
                    mma_tf32(c[i][j], al[i], bh[j]);
                }
        }
        __syncthreads();
    }

    // ---- epilogue
    int g = lane >> 2, t = lane & 3;
#pragma unroll
    for (int i = 0; i < 4; i++)
#pragma unroll
        for (int j = 0; j < NW; j++) {
            int m = m0 + wm * 64 + i * 16 + g;
            int n = n0 + wn * (BN_ / 4) + j * 8 + t * 2;
            float2 v0 = {c[i][j][0] * scale, c[i][j][1] * scale};
            float2 v1 = {c[i][j][2] * scale, c[i][j][3] * scale};
            *(float2*)(C + (size_t)m * ldc + n) = v0;
            *(float2*)(C + (size_t)(m + 8) * ldc + n) = v1;
        }
}

// ---------------- weight concat: 7 x (512,1024) -> g_wcat (3584,1024) ----------------
__global__ void copy_wcat_k(const float* __restrict__ w0, const float* __restrict__ w1,
                            const float* __restrict__ w2, const float* __restrict__ w3,
                            const float* __restrict__ w4, const float* __restrict__ w5,
                            const float* __restrict__ w6, float* __restrict__ dst)
{
    size_t idx = (size_t)blockIdx.x * blockDim.x + threadIdx.x;
    const size_t per = (size_t)512 * DM;
    if (idx >= 7 * per) return;
    int p = (int)(idx / per);
    size_t off = idx % per;
    const float* w = w0;
    if (p == 1) w = w1; else if (p == 2) w = w2; else if (p == 3) w = w3;
    else if (p == 4) w = w4; else if (p == 5) w = w5; else if (p == 6) w = w6;
    dst[idx] = w[off];
}

// ---------------- RoPE on slabs {0:q_sa, 1:k_sa, 3:qa, 4:ka} of g_proj ----------------
__global__ void rope_k(float* __restrict__ proj, const float* __restrict__ fc,
                       const float* __restrict__ fs)
{
    size_t idx = (size_t)blockIdx.x * blockDim.x + threadIdx.x;
    int m = idx & 31;
    int h = (idx >> 5) & 7;
    int p = (idx >> 8) & 3;
    size_t row = idx >> 10;
    if (row >= (size_t)MTOT) return;
    int s = (int)(row & (SS - 1));
    int pc = (p < 2) ? p : p + 1;     // {0,1,3,4}
    float* base = proj + row * PLD + pc * 512 + h * 64 + 2 * m;
    float c = fc[s * 32 + m];
    float sn = fs[s * 32 + m];
    float xr = base[0], xi = base[1];
    base[0] = xr * c - xi * sn;
    base[1] = xr * sn + xi * c;
}

// ---------------- in-place causal row softmax on (G, S, S) ----------------
__global__ void softmax_k(float* __restrict__ sc)
{
    int i = blockIdx.x;
    long long g = blockIdx.y;
    float* row = sc + (g * SS + (long long)i) * SS;
    int t = threadIdx.x;
    const int C = SS / 256;
    float vals[C];
    float mx = -3.4e38f;
#pragma unroll
    for (int c = 0; c < C; c++) {
        int j = t + c * 256;
        float v = (j <= i) ? row[j] : -3.4e38f;
        vals[c] = v;
        mx = fmaxf(mx, v);
    }
    __shared__ float red[256];
    red[t] = mx; __syncthreads();
    for (int o = 128; o > 0; o >>= 1) { if (t < o) red[t] = fmaxf(red[t], red[t + o]); __syncthreads(); }
    mx = red[0];
    __syncthreads();
    float sum = 0.f;
#pragma unroll
    for (int c = 0; c < C; c++) {
        float e = __expf(vals[c] - mx);
        vals[c] = e;
        sum += e;
    }
    red[t] = sum; __syncthreads();
    for (int o = 128; o > 0; o >>= 1) { if (t < o) red[t] += red[t + o]; __syncthreads(); }
    float inv = 1.0f / red[0];
#pragma unroll
    for (int c = 0; c < C; c++) {
        int j = t + c * 256;
        row[j] = vals[c] * inv;
    }
}

// ---------------- attended_rel[b,i,h,r] = sum_{j<=i} alpha[b,h,i,j] * rel[b,r,i,j] ----------------
__global__ void attrel_k(const float* __restrict__ alpha, const float* __restrict__ rel,
                         float* __restrict__ out)
{
    int i = blockIdx.x, b = blockIdx.y;
    int t = threadIdx.x;
    int o = t >> 2, stripe = t & 3;     // o = h*8 + r
    int h = o >> 3, r = o & 7;
    const float* arow = alpha + ((long long)(b * HH + h) * SS + i) * SS;
    const float* rrow = rel   + ((long long)(b * NREL + r) * SS + i) * SS;
    float acc = 0.f;
    for (int j = stripe; j <= i; j += 4) acc += arow[j] * rrow[j];
    __shared__ float red[256];
    red[t] = acc; __syncthreads();
    if (stripe == 0)
        out[((long long)b * SS + i) * 64 + o] = red[t] + red[t + 1] + red[t + 2] + red[t + 3];
}

// ---------------- ctx_ra += einsum('bihr,hdr->bihd', attrel, wr) ----------------
__global__ void relout_k(const float* __restrict__ attrel, const float* __restrict__ wr,
                         float* __restrict__ ctx)
{
    size_t idx = (size_t)blockIdx.x * blockDim.x + threadIdx.x;
    if (idx >= (size_t)MTOT * 512) return;
    int d = idx & 63;
    int h = (idx >> 6) & 7;
    size_t bi = idx >> 9;
    const float* ar = attrel + bi * 64 + h * 8;
    const float* w = wr + ((size_t)h * 64 + d) * 8;
    float v = 0.f;
#pragma unroll
    for (int r = 0; r < 8; r++) v += ar[r] * w[r];
    ctx[idx] += v;
}

// ---------------- launcher ----------------
extern "C" void kernel_launch(void* const* d_in, const int* in_sizes, int n_in,
                              void* d_out, int out_size)
{
    const float* x     = (const float*)d_in[0];
    const float* symb  = (const float*)d_in[1];
    const float* fc    = (const float*)d_in[2];
    const float* fs    = (const float*)d_in[3];
    const float* wq_sa = (const float*)d_in[4];
    const float* wk_sa = (const float*)d_in[5];
    const float* wv_sa = (const float*)d_in[6];
    const float* wo_sa = (const float*)d_in[7];
    const float* wq_at = (const float*)d_in[8];
    const float* wk_at = (const float*)d_in[9];
    const float* wq_rl = (const float*)d_in[10];
    const float* wk_rl = (const float*)d_in[11];
    const float* wr    = (const float*)d_in[12];
    const float* wv_ra = (const float*)d_in[13];
    const float* wo_ra = (const float*)d_in[14];
    float* out = (float*)d_out;

    float *wcat, *proj, *sv, *sc_sa, *sc_ra, *rel, *ctx_sa, *ctx_ra, *attrel;
    cudaGetSymbolAddress((void**)&wcat,   g_wcat);
    cudaGetSymbolAddress((void**)&proj,   g_proj);
    cudaGetSymbolAddress((void**)&sv,     g_sv);
    cudaGetSymbolAddress((void**)&sc_sa,  g_sc_sa);
    cudaGetSymbolAddress((void**)&sc_ra,  g_sc_ra);
    cudaGetSymbolAddress((void**)&rel,    g_rel);
    cudaGetSymbolAddress((void**)&ctx_sa, g_ctx_sa);
    cudaGetSymbolAddress((void**)&ctx_ra, g_ctx_ra);
    cudaGetSymbolAddress((void**)&attrel, g_attrel);

    dim3 tpb(256);
    const float scl = 0.125f;             // 1/sqrt(64), both attn and rel
    const long long bS  = (long long)SS * PLD;     // per-batch stride in proj
    const long long sHS = (long long)SS * SS;      // per-head score stride
    const long long sBS = (long long)HH * SS * SS; // per-batch score stride

    // fused input projections: proj = x @ Wcat^T  (4096 x 3584)
    copy_wcat_k<<<14336, 256>>>(wq_sa, wk_sa, wv_sa, wq_at, wk_at, wq_rl, wk_rl, wcat);
    gemm_tc<128, true, false, false><<<dim3(28, 32, 1), tpb>>>(
        x, DM, 0, 0, wcat, DM, 0, 0, proj, PLD, 0, 0, MTOT, PLD, DM, 1, 1.0f);
    // sv = symbols @ wv_ra^T
    gemm_tc<128, true, false, false><<<dim3(4, 32, 1), tpb>>>(
        symb, DM, 0, 0, wv_ra, DM, 0, 0, sv, 512, 0, 0, MTOT, 512, DM, 1, 1.0f);
    // RoPE on q_sa, k_sa, qa, ka
    rope_k<<<16384, 256>>>(proj, fc, fs);

    // causal score GEMMs (scale folded in)
    gemm_tc<128, true, true, false><<<dim3(16, 16, 16), tpb>>>(
        proj + 0 * 512, PLD, bS, 64, proj + 1 * 512, PLD, bS, 64,
        sc_sa, SS, sBS, sHS, SS, SS, 64, HH, scl);
    gemm_tc<128, true, true, false><<<dim3(16, 16, 16), tpb>>>(
        proj + 3 * 512, PLD, bS, 64, proj + 4 * 512, PLD, bS, 64,
        sc_ra, SS, sBS, sHS, SS, SS, 64, HH, scl);
    gemm_tc<128, true, true, false><<<dim3(16, 16, 16), tpb>>>(
        proj + 5 * 512, PLD, bS, 64, proj + 6 * 512, PLD, bS, 64,
        rel, SS, (long long)NREL * SS * SS, sHS, SS, SS, 64, NREL, scl);

    // in-place softmax -> alpha
    softmax_k<<<dim3(SS, BB * HH), 256>>>(sc_sa);
    softmax_k<<<dim3(SS, BB * HH), 256>>>(sc_ra);

    // ctx = alpha @ V (K-clamped to the causal range)
    gemm_tc<64, false, false, true><<<dim3(1, 16, 16), tpb>>>(
        sc_sa, SS, sBS, sHS, proj + 2 * 512, PLD, bS, 64,
        ctx_sa, 512, (long long)SS * 512, 64, SS, 64, SS, HH, 1.0f);
    gemm_tc<64, false, false, true><<<dim3(1, 16, 16), tpb>>>(
        sc_ra, SS, sBS, sHS, sv, 512, (long long)SS * 512, 64,
        ctx_ra, 512, (long long)SS * 512, 64, SS, 64, SS, HH, 1.0f);

    // attended_rel, then += wr contraction
    attrel_k<<<dim3(SS, BB), 256>>>(sc_ra, rel, attrel);
    relout_k<<<8192, 256>>>(attrel, wr, ctx_ra);

    // output projections, concatenated into d_out
    gemm_tc<128, true, false, false><<<dim3(4, 32, 1), tpb>>>(
        ctx_sa, 512, 0, 0, wo_sa, 512, 0, 0, out, DM, 0, 0, MTOT, 512, 512, 1, 1.0f);
    gemm_tc<128, true, false, false><<<dim3(4, 32, 1), tpb>>>(
        ctx_ra, 512, 0, 0, wo_ra, 512, 0, 0, out + 512, DM, 0, 0, MTOT, 512, 512, 1, 1.0f);
}

// round 7
// speedup vs baseline: 1.7477x; 1.7477x over previous
#include <cuda_runtime.h>
#include <cuda_bf16.h>
#include <cstdint>

#define BB 2
#define SS 2048
#define DM 1024
#define HH 8
#define HD 64
#define NREL 8
#define MTOT (BB*SS)          // 4096 rows (b,s flattened)
#define PLD 3584              // fused projection row stride (7*512)

// ---------------- scratch (device globals; no allocation allowed) ----------------
static __device__ float g_wcat[(size_t)7*512*DM];                 // 14 MB
static __device__ float g_proj[(size_t)MTOT*PLD];                 // 59 MB
static __device__ float g_sv[(size_t)MTOT*512];                   // 8.4 MB
static __device__ float g_sc_sa[(size_t)BB*HH*SS*SS];             // 268 MB
static __device__ float g_sc_ra[(size_t)BB*HH*SS*SS];             // 268 MB
static __device__ float g_rel[(size_t)BB*NREL*SS*SS];             // 268 MB
static __device__ float g_ctx_sa[(size_t)MTOT*512];               // 8.4 MB
static __device__ float g_ctx_ra[(size_t)MTOT*512];               // 8.4 MB
static __device__ float g_attrel[(size_t)MTOT*64];                // 1 MB

// ==================================================================================
// bf16x3 tensor-core GEMM via mma.sync.m16n8k16 (compiles at plain sm_103 target).
//   C = scale * A(M,K) * op(B), fp32 in/out. x = hi + lo (bf16):
//   D += Ah*Bh + Ah*Bl + Al*Bh, fp32 accumulation -> ~1e-5 rel error.
// Tile: BM=128 x BN_ x BK=32. 256 thr = 8 warps (2x4), warptile 64 x BN_/4.
// Fragment-ordered smem: per-lane A frag = 1 LDS.128, B frag = 1 LDS.64.
// TRANSB=true : B is (N,K) row-major.  TRANSB=false: B is (K,N) row-major (BN_=64).
// CAUSAL: skip tiles above diagonal. KCLAMP: K limited to m0+128.
// All dims are multiples of the tile dims.
// ==================================================================================
#define BKC 32

__device__ __forceinline__ void split2(float x, float y, uint32_t& hi, uint32_t& lo) {
    __nv_bfloat16 hx = __float2bfloat16_rn(x), hy = __float2bfloat16_rn(y);
    __nv_bfloat16 lx = __float2bfloat16_rn(x - __bfloat162float(hx));
    __nv_bfloat16 ly = __float2bfloat16_rn(y - __bfloat162float(hy));
    hi = (uint32_t)__bfloat16_as_ushort(hx) | ((uint32_t)__bfloat16_as_ushort(hy) << 16);
    lo = (uint32_t)__bfloat16_as_ushort(lx) | ((uint32_t)__bfloat16_as_ushort(ly) << 16);
}

__device__ __forceinline__ void mma_bf16(float* c, const uint32_t* a, const uint32_t* b) {
    asm volatile(
        "mma.sync.aligned.m16n8k16.row.col.f32.bf16.bf16.f32 "
        "{%0,%1,%2,%3}, {%4,%5,%6,%7}, {%8,%9}, {%0,%1,%2,%3};\n"
        : "+f"(c[0]), "+f"(c[1]), "+f"(c[2]), "+f"(c[3])
        : "r"(a[0]), "r"(a[1]), "r"(a[2]), "r"(a[3]), "r"(b[0]), "r"(b[1]));
}

template<int BN_, bool TRANSB, bool CAUSAL, bool KCLAMP>
__global__ __launch_bounds__(256)
void gemm_bf(const float* __restrict__ A, int lda, long long sAo, long long sAi,
             const float* __restrict__ B, int ldb, long long sBo, long long sBi,
             float* __restrict__ C, int ldc, long long sCo, long long sCi,
             int M, int N, int K, int inner, float scale)
{
    constexpr int NT8 = BN_ / 8;              // 8-wide B tiles across BN_
    constexpr int NT  = NT8 / 4;              // B tiles per warp (4 warp cols)
    constexpr int ALD = 4;                    // A float4 loads / thread (128*32/4/256)
    constexpr int BLD = BN_ / 32;             // B float4 loads / thread (TRANSB)
    constexpr int SB0 = 4096;                 // u32 offset of B region
    static_assert(TRANSB || BN_ == 64, "NN loader assumes BN_==64");

    // A: [h][k16][mt(8)][lane(32)][reg(4)]  = 4096 u32 (16KB)
    // B: [h][k16][bt(NT8)][lane(32)][reg(2)] = NT8*256 u32
    __shared__ uint32_t sm[4096 + NT8 * 256];

    int bx = blockIdx.x, by = blockIdx.y, bz = blockIdx.z;
    if (CAUSAL && bx > by) return;
    int outer = bz / inner, in = bz % inner;
    A += outer * sAo + (long long)in * sAi;
    B += outer * sBo + (long long)in * sBi;
    C += outer * sCo + (long long)in * sCi;
    int m0 = by * 128, n0 = bx * BN_;
    int kend = KCLAMP ? min(K, m0 + 128) : K;
    int nit = kend >> 5;

    int tid = threadIdx.x, wid = tid >> 5, lane = tid & 31;
    int wm = wid >> 2, wn = wid & 3;

    auto sAi_ = [](int h, int k16, int mt, int ln, int rg) {
        return (((h * 2 + k16) * 8 + mt) * 32 + ln) * 4 + rg;
    };
    auto sBi_ = [](int h, int k16, int bt, int ln, int rg) {
        return SB0 + (((h * 2 + k16) * NT8 + bt) * 32 + ln) * 2 + rg;
    };

    float c[4][NT][4];
#pragma unroll
    for (int i = 0; i < 4; i++)
#pragma unroll
        for (int j = 0; j < NT; j++)
#pragma unroll
            for (int r = 0; r < 4; r++) c[i][j][r] = 0.f;

    float4 rA[ALD];
    float4 rB[TRANSB ? BLD : 2];

    // ---- global -> register prefetch of one K=32 slab
    auto g2r = [&](int kt) {
        int k0 = kt << 5;
#pragma unroll
        for (int it = 0; it < ALD; it++) {
            int idx = tid + it * 256;
            int row = idx >> 3, kq = (idx & 7) << 2;
            rA[it] = *(const float4*)(A + (size_t)(m0 + row) * lda + k0 + kq);
        }
        if (TRANSB) {
#pragma unroll
            for (int it = 0; it < BLD; it++) {
                int idx = tid + it * 256;
                int n = idx >> 3, kq = (idx & 7) << 2;
                rB[it] = *(const float4*)(B + (size_t)(n0 + n) * ldb + k0 + kq);
            }
        } else {
            // B (K,N): each thread gathers 8 k's for one n
            int n = tid & 63, kb = (tid >> 6) * 8;
            const float* Bb = B + (size_t)(k0 + kb) * ldb + n0 + n;
            float v[8];
#pragma unroll
            for (int kk = 0; kk < 8; kk++) v[kk] = Bb[(size_t)kk * ldb];
            rB[0] = make_float4(v[0], v[1], v[2], v[3]);
            rB[1] = make_float4(v[4], v[5], v[6], v[7]);
        }
    };

    // ---- register -> fragment-ordered smem (hi/lo bf16 split)
    auto sts = [&]() {
#pragma unroll
        for (int it = 0; it < ALD; it++) {
            int idx = tid + it * 256;
            int row = idx >> 3, kq = (idx & 7) << 2;
            int k16 = kq >> 4, kk0 = kq & 15;
            int mt = row >> 4, r = row & 15, g = r & 7, half = r >> 3;
            int t0 = (kk0 & 7) >> 1;
            int rb = half + ((kk0 & 8) ? 2 : 0);
            uint32_t h0, l0, h1, l1;
            split2(rA[it].x, rA[it].y, h0, l0);
            split2(rA[it].z, rA[it].w, h1, l1);
            int ln = g * 4 + t0;
            sm[sAi_(0, k16, mt, ln, rb)]     = h0;
            sm[sAi_(1, k16, mt, ln, rb)]     = l0;
            sm[sAi_(0, k16, mt, ln + 1, rb)] = h1;
            sm[sAi_(1, k16, mt, ln + 1, rb)] = l1;
        }
        if (TRANSB) {
#pragma unroll
            for (int it = 0; it < BLD; it++) {
                int idx = tid + it * 256;
                int n = idx >> 3, kq = (idx & 7) << 2;
                int k16 = kq >> 4, kk0 = kq & 15;
                int bt = n >> 3, g = n & 7;
                int t0 = (kk0 & 7) >> 1;
                int rb = (kk0 & 8) ? 1 : 0;
                uint32_t h0, l0, h1, l1;
                split2(rB[it].x, rB[it].y, h0, l0);
                split2(rB[it].z, rB[it].w, h1, l1);
                int ln = g * 4 + t0;
                sm[sBi_(0, k16, bt, ln, rb)]     = h0;
                sm[sBi_(1, k16, bt, ln, rb)]     = l0;
                sm[sBi_(0, k16, bt, ln + 1, rb)] = h1;
                sm[sBi_(1, k16, bt, ln + 1, rb)] = l1;
            }
        } else {
            int n = tid & 63, kb = (tid >> 6) * 8;
            int bt = n >> 3, g = n & 7;
            float v[8] = {rB[0].x, rB[0].y, rB[0].z, rB[0].w,
                          rB[1].x, rB[1].y, rB[1].z, rB[1].w};
#pragma unroll
            for (int kk2 = 0; kk2 < 8; kk2++) {
                int k = kb + kk2;
                int k16 = k >> 4, kk = k & 15;
                int t = (kk & 7) >> 1, e = kk & 1, rg = (kk & 8) ? 1 : 0;
                int ln = g * 4 + t;
                __nv_bfloat16 hv = __float2bfloat16_rn(v[kk2]);
                __nv_bfloat16 lv = __float2bfloat16_rn(v[kk2] - __bfloat162float(hv));
                ((__nv_bfloat16*)&sm[sBi_(0, k16, bt, ln, rg)])[e] = hv;
                ((__nv_bfloat16*)&sm[sBi_(1, k16, bt, ln, rg)])[e] = lv;
            }
        }
    };

    g2r(0);
    for (int kt = 0; kt < nit; kt++) {
        sts();
        __syncthreads();
        if (kt + 1 < nit) g2r(kt + 1);

#pragma unroll
        for (int k16 = 0; k16 < 2; k16++) {
            uint32_t ah[4][4], al[4][4], bh[NT][2], bl[NT][2];
#pragma unroll
            for (int i = 0; i < 4; i++) {
                *(uint4*)ah[i] = *(const uint4*)&sm[sAi_(0, k16, wm * 4 + i, lane, 0)];
                *(uint4*)al[i] = *(const uint4*)&sm[sAi_(1, k16, wm * 4 + i, lane, 0)];
            }
#pragma unroll
            for (int j = 0; j < NT; j++) {
                *(uint2*)bh[j] = *(const uint2*)&sm[sBi_(0, k16, wn * NT + j, lane, 0)];
                *(uint2*)bl[j] = *(const uint2*)&sm[sBi_(1, k16, wn * NT + j, lane, 0)];
            }
#pragma unroll
            for (int i = 0; i < 4; i++)
#pragma unroll
                for (int j = 0; j < NT; j++) {
                    mma_bf16(c[i][j], ah[i], bh[j]);
                    mma_bf16(c[i][j], ah[i], bl[j]);
                    mma_bf16(c[i][j], al[i], bh[j]);
                }
        }
        __syncthreads();
    }

    // ---- epilogue
    int g = lane >> 2, t = lane & 3;
#pragma unroll
    for (int i = 0; i < 4; i++)
#pragma unroll
        for (int j = 0; j < NT; j++) {
            int m = m0 + wm * 64 + i * 16 + g;
            int n = n0 + wn * (BN_ / 4) + j * 8 + t * 2;
            float2 v0 = {c[i][j][0] * scale, c[i][j][1] * scale};
            float2 v1 = {c[i][j][2] * scale, c[i][j][3] * scale};
            *(float2*)(C + (size_t)m * ldc + n) = v0;
            *(float2*)(C + (size_t)(m + 8) * ldc + n) = v1;
        }
}

// ---------------- weight concat: 7 x (512,1024) -> g_wcat (3584,1024) ----------------
__global__ void copy_wcat_k(const float* __restrict__ w0, const float* __restrict__ w1,
                            const float* __restrict__ w2, const float* __restrict__ w3,
                            const float* __restrict__ w4, const float* __restrict__ w5,
                            const float* __restrict__ w6, float* __restrict__ dst)
{
    size_t idx = (size_t)blockIdx.x * blockDim.x + threadIdx.x;
    const size_t per = (size_t)512 * DM;
    if (idx >= 7 * per) return;
    int p = (int)(idx / per);
    size_t off = idx % per;
    const float* w = w0;
    if (p == 1) w = w1; else if (p == 2) w = w2; else if (p == 3) w = w3;
    else if (p == 4) w = w4; else if (p == 5) w = w5; else if (p == 6) w = w6;
    dst[idx] = w[off];
}

// ---------------- RoPE on slabs {0:q_sa, 1:k_sa, 3:qa, 4:ka} of g_proj ----------------
__global__ void rope_k(float* __restrict__ proj, const float* __restrict__ fc,
                       const float* __restrict__ fs)
{
    size_t idx = (size_t)blockIdx.x * blockDim.x + threadIdx.x;
    int m = idx & 31;
    int h = (idx >> 5) & 7;
    int p = (idx >> 8) & 3;
    size_t row = idx >> 10;
    if (row >= (size_t)MTOT) return;
    int s = (int)(row & (SS - 1));
    int pc = (p < 2) ? p : p + 1;     // {0,1,3,4}
    float* base = proj + row * PLD + pc * 512 + h * 64 + 2 * m;
    float c = fc[s * 32 + m];
    float sn = fs[s * 32 + m];
    float xr = base[0], xi = base[1];
    base[0] = xr * c - xi * sn;
    base[1] = xr * sn + xi * c;
}

// ---------------- in-place causal row softmax on (G, S, S) ----------------
__global__ void softmax_k(float* __restrict__ sc)
{
    int i = blockIdx.x;
    long long g = blockIdx.y;
    float* row = sc + (g * SS + (long long)i) * SS;
    int t = threadIdx.x;
    const int C = SS / 256;
    float vals[C];
    float mx = -3.4e38f;
#pragma unroll
    for (int c = 0; c < C; c++) {
        int j = t + c * 256;
        float v = (j <= i) ? row[j] : -3.4e38f;
        vals[c] = v;
        mx = fmaxf(mx, v);
    }
    __shared__ float red[256];
    red[t] = mx; __syncthreads();
    for (int o = 128; o > 0; o >>= 1) { if (t < o) red[t] = fmaxf(red[t], red[t + o]); __syncthreads(); }
    mx = red[0];
    __syncthreads();
    float sum = 0.f;
#pragma unroll
    for (int c = 0; c < C; c++) {
        float e = __expf(vals[c] - mx);
        vals[c] = e;
        sum += e;
    }
    red[t] = sum; __syncthreads();
    for (int o = 128; o > 0; o >>= 1) { if (t < o) red[t] += red[t + o]; __syncthreads(); }
    float inv = 1.0f / red[0];
#pragma unroll
    for (int c = 0; c < C; c++) {
        int j = t + c * 256;
        row[j] = vals[c] * inv;
    }
}

// ---------------- attended_rel[b,i,h,r] = sum_{j<=i} alpha[b,h,i,j] * rel[b,r,i,j] ----------------
__global__ void attrel_k(const float* __restrict__ alpha, const float* __restrict__ rel,
                         float* __restrict__ out)
{
    int i = blockIdx.x, b = blockIdx.y;
    int t = threadIdx.x;
    int o = t >> 2, stripe = t & 3;     // o = h*8 + r
    int h = o >> 3, r = o & 7;
    const float* arow = alpha + ((long long)(b * HH + h) * SS + i) * SS;
    const float* rrow = rel   + ((long long)(b * NREL + r) * SS + i) * SS;
    float acc = 0.f;
    for (int j = stripe; j <= i; j += 4) acc += arow[j] * rrow[j];
    __shared__ float red[256];
    red[t] = acc; __syncthreads();
    if (stripe == 0)
        out[((long long)b * SS + i) * 64 + o] = red[t] + red[t + 1] + red[t + 2] + red[t + 3];
}

// ---------------- ctx_ra += einsum('bihr,hdr->bihd', attrel, wr) ----------------
__global__ void relout_k(const float* __restrict__ attrel, const float* __restrict__ wr,
                         float* __restrict__ ctx)
{
    size_t idx = (size_t)blockIdx.x * blockDim.x + threadIdx.x;
    if (idx >= (size_t)MTOT * 512) return;
    int d = idx & 63;
    int h = (idx >> 6) & 7;
    size_t bi = idx >> 9;
    const float* ar = attrel + bi * 64 + h * 8;
    const float* w = wr + ((size_t)h * 64 + d) * 8;
    float v = 0.f;
#pragma unroll
    for (int r = 0; r < 8; r++) v += ar[r] * w[r];
    ctx[idx] += v;
}

// ---------------- launcher ----------------
extern "C" void kernel_launch(void* const* d_in, const int* in_sizes, int n_in,
                              void* d_out, int out_size)
{
    const float* x     = (const float*)d_in[0];
    const float* symb  = (const float*)d_in[1];
    const float* fc    = (const float*)d_in[2];
    const float* fs    = (const float*)d_in[3];
    const float* wq_sa = (const float*)d_in[4];
    const float* wk_sa = (const float*)d_in[5];
    const float* wv_sa = (const float*)d_in[6];
    const float* wo_sa = (const float*)d_in[7];
    const float* wq_at = (const float*)d_in[8];
    const float* wk_at = (const float*)d_in[9];
    const float* wq_rl = (const float*)d_in[10];
    const float* wk_rl = (const float*)d_in[11];
    const float* wr    = (const float*)d_in[12];
    const float* wv_ra = (const float*)d_in[13];
    const float* wo_ra = (const float*)d_in[14];
    float* out = (float*)d_out;

    float *wcat, *proj, *sv, *sc_sa, *sc_ra, *rel, *ctx_sa, *ctx_ra, *attrel;
    cudaGetSymbolAddress((void**)&wcat,   g_wcat);
    cudaGetSymbolAddress((void**)&proj,   g_proj);
    cudaGetSymbolAddress((void**)&sv,     g_sv);
    cudaGetSymbolAddress((void**)&sc_sa,  g_sc_sa);
    cudaGetSymbolAddress((void**)&sc_ra,  g_sc_ra);
    cudaGetSymbolAddress((void**)&rel,    g_rel);
    cudaGetSymbolAddress((void**)&ctx_sa, g_ctx_sa);
    cudaGetSymbolAddress((void**)&ctx_ra, g_ctx_ra);
    cudaGetSymbolAddress((void**)&attrel, g_attrel);

    dim3 tpb(256);
    const float scl = 0.125f;                       // 1/sqrt(64)
    const long long bS  = (long long)SS * PLD;      // per-batch stride in proj
    const long long sHS = (long long)SS * SS;       // per-head score stride
    const long long sBS = (long long)HH * SS * SS;  // per-batch score stride

    // fused input projections: proj = x @ Wcat^T  (4096 x 3584, K=1024)
    copy_wcat_k<<<14336, 256>>>(wq_sa, wk_sa, wv_sa, wq_at, wk_at, wq_rl, wk_rl, wcat);
    gemm_bf<128, true, false, false><<<dim3(28, 32, 1), tpb>>>(
        x, DM, 0, 0, wcat, DM, 0, 0, proj, PLD, 0, 0, MTOT, PLD, DM, 1, 1.0f);
    // sv = symbols @ wv_ra^T
    gemm_bf<128, true, false, false><<<dim3(4, 32, 1), tpb>>>(
        symb, DM, 0, 0, wv_ra, DM, 0, 0, sv, 512, 0, 0, MTOT, 512, DM, 1, 1.0f);
    // RoPE on q_sa, k_sa, qa, ka
    rope_k<<<16384, 256>>>(proj, fc, fs);

    // causal score GEMMs (K=64, scale folded into epilogue)
    gemm_bf<128, true, true, false><<<dim3(16, 16, 16), tpb>>>(
        proj + 0 * 512, PLD, bS, 64, proj + 1 * 512, PLD, bS, 64,
        sc_sa, SS, sBS, sHS, SS, SS, 64, HH, scl);
    gemm_bf<128, true, true, false><<<dim3(16, 16, 16), tpb>>>(
        proj + 3 * 512, PLD, bS, 64, proj + 4 * 512, PLD, bS, 64,
        sc_ra, SS, sBS, sHS, SS, SS, 64, HH, scl);
    gemm_bf<128, true, true, false><<<dim3(16, 16, 16), tpb>>>(
        proj + 5 * 512, PLD, bS, 64, proj + 6 * 512, PLD, bS, 64,
        rel, SS, (long long)NREL * SS * SS, sHS, SS, SS, 64, NREL, scl);

    // in-place softmax -> alpha
    softmax_k<<<dim3(SS, BB * HH), 256>>>(sc_sa);
    softmax_k<<<dim3(SS, BB * HH), 256>>>(sc_ra);

    // ctx = alpha @ V (K clamped to causal range)
    gemm_bf<64, false, false, true><<<dim3(1, 16, 16), tpb>>>(
        sc_sa, SS, sBS, sHS, proj + 2 * 512, PLD, bS, 64,
        ctx_sa, 512, (long long)SS * 512, 64, SS, 64, SS, HH, 1.0f);
    gemm_bf<64, false, false, true><<<dim3(1, 16, 16), tpb>>>(
        sc_ra, SS, sBS, sHS, sv, 512, (long long)SS * 512, 64,
        ctx_ra, 512, (long long)SS * 512, 64, SS, 64, SS, HH, 1.0f);

    // attended_rel, then += wr contraction
    attrel_k<<<dim3(SS, BB), 256>>>(sc_ra, rel, attrel);
    relout_k<<<8192, 256>>>(attrel, wr, ctx_ra);

    // output projections, concatenated into d_out (K=512)
    gemm_bf<128, true, false, false><<<dim3(4, 32, 1), tpb>>>(
        ctx_sa, 512, 0, 0, wo_sa, 512, 0, 0, out, DM, 0, 0, MTOT, 512, 512, 1, 1.0f);
    gemm_bf<128, true, false, false><<<dim3(4, 32, 1), tpb>>>(
        ctx_ra, 512, 0, 0, wo_ra, 512, 0, 0, out + 512, DM, 0, 0, MTOT, 512, 512, 1, 1.0f);
}

// round 11
// speedup vs baseline: 1.9947x; 1.1413x over previous
#include <cuda_runtime.h>
#include <cuda_bf16.h>
#include <cstdint>

#define BB 2
#define SS 2048
#define DM 1024
#define HH 8
#define HD 64
#define NREL 8
#define MTOT (BB*SS)          // 4096 rows (b,s flattened)
#define PLD 3584              // fused projection row stride (7*512)

// ---------------- scratch (device globals; no allocation allowed) ----------------
static __device__ float g_wcat[(size_t)7*512*DM];                 // 14 MB
static __device__ float g_proj[(size_t)MTOT*PLD];                 // 59 MB
static __device__ float g_sv[(size_t)MTOT*512];                   // 8.4 MB
static __device__ float g_sc_sa[(size_t)BB*HH*SS*SS];             // 268 MB
static __device__ float g_sc_ra[(size_t)BB*HH*SS*SS];             // 268 MB
static __device__ float g_rel[(size_t)BB*NREL*SS*SS];             // 268 MB
static __device__ float g_ctx_sa[(size_t)MTOT*512];               // 8.4 MB
static __device__ float g_ctx_ra[(size_t)MTOT*512];               // 8.4 MB
static __device__ float g_attrel[(size_t)MTOT*64];                // 1 MB

// ==================================================================================
// bf16x3 tensor-core GEMM via mma.sync.m16n8k16.
//   C = scale * A(M,K) * op(B), fp32 in/out. x = hi + lo (bf16):
//   D += Ah*Bh + Ah*Bl + Al*Bh, fp32 accumulation -> ~1e-5 rel error.
// Tile: BM=128 x BN_ x BK=32. 256 thr = 8 warps (2x4), warptile 64 x BN_/4.
// Fragment-ordered smem: per-lane A frag = 1 LDS.128, B frag = 1 LDS.64.
// TRANSB=true : B is (N,K) row-major.  TRANSB=false: B is (K,N) row-major (BN_=64).
// CAUSAL: skip tiles above diagonal. KCLAMP: K limited to m0+128.
// ==================================================================================
__device__ __forceinline__ void split2(float x, float y, uint32_t& hi, uint32_t& lo) {
    __nv_bfloat16 hx = __float2bfloat16_rn(x), hy = __float2bfloat16_rn(y);
    __nv_bfloat16 lx = __float2bfloat16_rn(x - __bfloat162float(hx));
    __nv_bfloat16 ly = __float2bfloat16_rn(y - __bfloat162float(hy));
    hi = (uint32_t)__bfloat16_as_ushort(hx) | ((uint32_t)__bfloat16_as_ushort(hy) << 16);
    lo = (uint32_t)__bfloat16_as_ushort(lx) | ((uint32_t)__bfloat16_as_ushort(ly) << 16);
}

__device__ __forceinline__ void mma_bf16(float* c, const uint32_t* a, const uint32_t* b) {
    asm volatile(
        "mma.sync.aligned.m16n8k16.row.col.f32.bf16.bf16.f32 "
        "{%0,%1,%2,%3}, {%4,%5,%6,%7}, {%8,%9}, {%0,%1,%2,%3};\n"
        : "+f"(c[0]), "+f"(c[1]), "+f"(c[2]), "+f"(c[3])
        : "r"(a[0]), "r"(a[1]), "r"(a[2]), "r"(a[3]), "r"(b[0]), "r"(b[1]));
}

template<int BN_, bool TRANSB, bool CAUSAL, bool KCLAMP>
__global__ __launch_bounds__(256)
void gemm_bf(const float* __restrict__ A, int lda, long long sAo, long long sAi,
             const float* __restrict__ B, int ldb, long long sBo, long long sBi,
             float* __restrict__ C, int ldc, long long sCo, long long sCi,
             int M, int N, int K, int inner, float scale)
{
    constexpr int NT8 = BN_ / 8;              // 8-wide B tiles across BN_
    constexpr int NT  = NT8 / 4;              // B tiles per warp (4 warp cols)
    constexpr int ALD = 4;                    // A float4 loads / thread
    constexpr int BLD = BN_ / 32;             // B float4 loads / thread (TRANSB)
    constexpr int SB0 = 4096;                 // u32 offset of B region
    static_assert(TRANSB || BN_ == 64, "NN loader assumes BN_==64");

    __shared__ uint32_t sm[4096 + NT8 * 256];

    int bx = blockIdx.x, by = blockIdx.y, bz = blockIdx.z;
    if (CAUSAL && bx > by) return;
    int outer = bz / inner, in = bz % inner;
    A += outer * sAo + (long long)in * sAi;
    B += outer * sBo + (long long)in * sBi;
    C += outer * sCo + (long long)in * sCi;
    int m0 = by * 128, n0 = bx * BN_;
    int kend = KCLAMP ? min(K, m0 + 128) : K;
    int nit = kend >> 5;

    int tid = threadIdx.x, wid = tid >> 5, lane = tid & 31;
    int wm = wid >> 2, wn = wid & 3;

    auto sAi_ = [](int h, int k16, int mt, int ln, int rg) {
        return (((h * 2 + k16) * 8 + mt) * 32 + ln) * 4 + rg;
    };
    auto sBi_ = [](int h, int k16, int bt, int ln, int rg) {
        return SB0 + (((h * 2 + k16) * NT8 + bt) * 32 + ln) * 2 + rg;
    };

    float c[4][NT][4];
#pragma unroll
    for (int i = 0; i < 4; i++)
#pragma unroll
        for (int j = 0; j < NT; j++)
#pragma unroll
            for (int r = 0; r < 4; r++) c[i][j][r] = 0.f;

    float4 rA[ALD];
    float4 rB[TRANSB ? BLD : 2];

    auto g2r = [&](int kt) {
        int k0 = kt << 5;
#pragma unroll
        for (int it = 0; it < ALD; it++) {
            int idx = tid + it * 256;
            int row = idx >> 3, kq = (idx & 7) << 2;
            rA[it] = *(const float4*)(A + (size_t)(m0 + row) * lda + k0 + kq);
        }
        if (TRANSB) {
#pragma unroll
            for (int it = 0; it < BLD; it++) {
                int idx = tid + it * 256;
                int n = idx >> 3, kq = (idx & 7) << 2;
                rB[it] = *(const float4*)(B + (size_t)(n0 + n) * ldb + k0 + kq);
            }
        } else {
            int n = tid & 63, kb = (tid >> 6) * 8;
            const float* Bb = B + (size_t)(k0 + kb) * ldb + n0 + n;
            float v[8];
#pragma unroll
            for (int kk = 0; kk < 8; kk++) v[kk] = Bb[(size_t)kk * ldb];
            rB[0] = make_float4(v[0], v[1], v[2], v[3]);
            rB[1] = make_float4(v[4], v[5], v[6], v[7]);
        }
    };

    auto sts = [&]() {
#pragma unroll
        for (int it = 0; it < ALD; it++) {
            int idx = tid + it * 256;
            int row = idx >> 3, kq = (idx & 7) << 2;
            int k16 = kq >> 4, kk0 = kq & 15;
            int mt = row >> 4, r = row & 15, g = r & 7, half = r >> 3;
            int t0 = (kk0 & 7) >> 1;
            int rb = half + ((kk0 & 8) ? 2 : 0);
            uint32_t h0, l0, h1, l1;
            split2(rA[it].x, rA[it].y, h0, l0);
            split2(rA[it].z, rA[it].w, h1, l1);
            int ln = g * 4 + t0;
            sm[sAi_(0, k16, mt, ln, rb)]     = h0;
            sm[sAi_(1, k16, mt, ln, rb)]     = l0;
            sm[sAi_(0, k16, mt, ln + 1, rb)] = h1;
            sm[sAi_(1, k16, mt, ln + 1, rb)] = l1;
        }
        if (TRANSB) {
#pragma unroll
            for (int it = 0; it < BLD; it++) {
                int idx = tid + it * 256;
                int n = idx >> 3, kq = (idx & 7) << 2;
                int k16 = kq >> 4, kk0 = kq & 15;
                int bt = n >> 3, g = n & 7;
                int t0 = (kk0 & 7) >> 1;
                int rb = (kk0 & 8) ? 1 : 0;
                uint32_t h0, l0, h1, l1;
                split2(rB[it].x, rB[it].y, h0, l0);
                split2(rB[it].z, rB[it].w, h1, l1);
                int ln = g * 4 + t0;
                sm[sBi_(0, k16, bt, ln, rb)]     = h0;
                sm[sBi_(1, k16, bt, ln, rb)]     = l0;
                sm[sBi_(0, k16, bt, ln + 1, rb)] = h1;
                sm[sBi_(1, k16, bt, ln + 1, rb)] = l1;
            }
        } else {
            int n = tid & 63, kb = (tid >> 6) * 8;
            int bt = n >> 3, g = n & 7;
            float v[8] = {rB[0].x, rB[0].y, rB[0].z, rB[0].w,
                          rB[1].x, rB[1].y, rB[1].z, rB[1].w};
#pragma unroll
            for (int kk2 = 0; kk2 < 8; kk2++) {
                int k = kb + kk2;
                int k16 = k >> 4, kk = k & 15;
                int t = (kk & 7) >> 1, e = kk & 1, rg = (kk & 8) ? 1 : 0;
                int ln = g * 4 + t;
                __nv_bfloat16 hv = __float2bfloat16_rn(v[kk2]);
                __nv_bfloat16 lv = __float2bfloat16_rn(v[kk2] - __bfloat162float(hv));
                ((__nv_bfloat16*)&sm[sBi_(0, k16, bt, ln, rg)])[e] = hv;
                ((__nv_bfloat16*)&sm[sBi_(1, k16, bt, ln, rg)])[e] = lv;
            }
        }
    };

    g2r(0);
    for (int kt = 0; kt < nit; kt++) {
        sts();
        __syncthreads();
        if (kt + 1 < nit) g2r(kt + 1);

#pragma unroll
        for (int k16 = 0; k16 < 2; k16++) {
            uint32_t ah[4][4], al[4][4], bh[NT][2], bl[NT][2];
#pragma unroll
            for (int i = 0; i < 4; i++) {
                *(uint4*)ah[i] = *(const uint4*)&sm[sAi_(0, k16, wm * 4 + i, lane, 0)];
                *(uint4*)al[i] = *(const uint4*)&sm[sAi_(1, k16, wm * 4 + i, lane, 0)];
            }
#pragma unroll
            for (int j = 0; j < NT; j++) {
                *(uint2*)bh[j] = *(const uint2*)&sm[sBi_(0, k16, wn * NT + j, lane, 0)];
                *(uint2*)bl[j] = *(const uint2*)&sm[sBi_(1, k16, wn * NT + j, lane, 0)];
            }
#pragma unroll
            for (int i = 0; i < 4; i++)
#pragma unroll
                for (int j = 0; j < NT; j++) {
                    mma_bf16(c[i][j], ah[i], bh[j]);
                    mma_bf16(c[i][j], ah[i], bl[j]);
                    mma_bf16(c[i][j], al[i], bh[j]);
                }
        }
        __syncthreads();
    }

    int g = lane >> 2, t = lane & 3;
#pragma unroll
    for (int i = 0; i < 4; i++)
#pragma unroll
        for (int j = 0; j < NT; j++) {
            int m = m0 + wm * 64 + i * 16 + g;
            int n = n0 + wn * (BN_ / 4) + j * 8 + t * 2;
            float2 v0 = {c[i][j][0] * scale, c[i][j][1] * scale};
            float2 v1 = {c[i][j][2] * scale, c[i][j][3] * scale};
            *(float2*)(C + (size_t)m * ldc + n) = v0;
            *(float2*)(C + (size_t)(m + 8) * ldc + n) = v1;
        }
}

// ---------------- weight concat: 7 x (512,1024) -> g_wcat (3584,1024) ----------------
__global__ void copy_wcat_k(const float* __restrict__ w0, const float* __restrict__ w1,
                            const float* __restrict__ w2, const float* __restrict__ w3,
                            const float* __restrict__ w4, const float* __restrict__ w5,
                            const float* __restrict__ w6, float* __restrict__ dst)
{
    size_t idx = (size_t)blockIdx.x * blockDim.x + threadIdx.x;
    const size_t per = (size_t)512 * DM;
    if (idx >= 7 * per) return;
    int p = (int)(idx / per);
    size_t off = idx % per;
    const float* w = w0;
    if (p == 1) w = w1; else if (p == 2) w = w2; else if (p == 3) w = w3;
    else if (p == 4) w = w4; else if (p == 5) w = w5; else if (p == 6) w = w6;
    dst[idx] = w[off];
}

// ---------------- RoPE on slabs {0:q_sa, 1:k_sa, 3:qa, 4:ka} of g_proj ----------------
__global__ void rope_k(float* __restrict__ proj, const float* __restrict__ fc,
                       const float* __restrict__ fs)
{
    size_t idx = (size_t)blockIdx.x * blockDim.x + threadIdx.x;
    int m = idx & 31;
    int h = (idx >> 5) & 7;
    int p = (idx >> 8) & 3;
    size_t row = idx >> 10;
    if (row >= (size_t)MTOT) return;
    int s = (int)(row & (SS - 1));
    int pc = (p < 2) ? p : p + 1;     // {0,1,3,4}
    float* base = proj + row * PLD + pc * 512 + h * 64 + 2 * m;
    float c = fc[s * 32 + m];
    float sn = fs[s * 32 + m];
    float xr = base[0], xi = base[1];
    base[0] = xr * c - xi * sn;
    base[1] = xr * sn + xi * c;
}

// ---------------- in-place causal row softmax on (G, S, S) ----------------
// Writes only the causal band [0, ((i>>7)+1)*128): downstream consumers
// (KCLAMP alpha@V and attrel) never read beyond the 128-wide diagonal band.
__global__ void softmax_k(float* __restrict__ sc)
{
    int i = blockIdx.x;
    long long g = blockIdx.y;
    float* row = sc + (g * SS + (long long)i) * SS;
    int t = threadIdx.x;
    const int C = SS / 256;
    float vals[C];
    float mx = -3.4e38f;
#pragma unroll
    for (int c = 0; c < C; c++) {
        int j = t + c * 256;
        float v = (j <= i) ? row[j] : -3.4e38f;
        vals[c] = v;
        mx = fmaxf(mx, v);
    }
    __shared__ float red[256];
    red[t] = mx; __syncthreads();
    for (int o = 128; o > 0; o >>= 1) { if (t < o) red[t] = fmaxf(red[t], red[t + o]); __syncthreads(); }
    mx = red[0];
    __syncthreads();
    float sum = 0.f;
#pragma unroll
    for (int c = 0; c < C; c++) {
        float e = __expf(vals[c] - mx);
        vals[c] = e;
        sum += e;
    }
    red[t] = sum; __syncthreads();
    for (int o = 128; o > 0; o >>= 1) { if (t < o) red[t] += red[t + o]; __syncthreads(); }
    float inv = 1.0f / red[0];
    int wlim = ((i >> 7) + 1) << 7;      // causal band end (multiple of 128)
#pragma unroll
    for (int c = 0; c < C; c++) {
        int j = t + c * 256;
        if (j < wlim) row[j] = vals[c] * inv;
    }
}

// ---------------- attended_rel[b,i,h,r] = sum_{j<=i} alpha[b,h,i,j] * rel[b,r,i,j] ----------------
__global__ void attrel_k(const float* __restrict__ alpha, const float* __restrict__ rel,
                         float* __restrict__ out)
{
    int i = blockIdx.x, b = blockIdx.y;
    int t = threadIdx.x;
    int o = t >> 2, stripe = t & 3;     // o = h*8 + r
    int h = o >> 3, r = o & 7;
    const float* arow = alpha + ((long long)(b * HH + h) * SS + i) * SS;
    const float* rrow = rel   + ((long long)(b * NREL + r) * SS + i) * SS;
    float acc = 0.f;
    for (int j = stripe; j <= i; j += 4) acc += arow[j] * rrow[j];
    __shared__ float red[256];
    red[t] = acc; __syncthreads();
    if (stripe == 0)
        out[((long long)b * SS + i) * 64 + o] = red[t] + red[t + 1] + red[t + 2] + red[t + 3];
}

// ---------------- ctx_ra += einsum('bihr,hdr->bihd', attrel, wr) ----------------
__global__ void relout_k(const float* __restrict__ attrel, const float* __restrict__ wr,
                         float* __restrict__ ctx)
{
    size_t idx = (size_t)blockIdx.x * blockDim.x + threadIdx.x;
    if (idx >= (size_t)MTOT * 512) return;
    int d = idx & 63;
    int h = (idx >> 6) & 7;
    size_t bi = idx >> 9;
    const float* ar = attrel + bi * 64 + h * 8;
    const float* w = wr + ((size_t)h * 64 + d) * 8;
    float v = 0.f;
#pragma unroll
    for (int r = 0; r < 8; r++) v += ar[r] * w[r];
    ctx[idx] += v;
}

// ---------------- launcher (multi-stream fork/join, graph-capture safe) ----------------
extern "C" void kernel_launch(void* const* d_in, const int* in_sizes, int n_in,
                              void* d_out, int out_size)
{
    const float* x     = (const float*)d_in[0];
    const float* symb  = (const float*)d_in[1];
    const float* fc    = (const float*)d_in[2];
    const float* fs    = (const float*)d_in[3];
    const float* wq_sa = (const float*)d_in[4];
    const float* wk_sa = (const float*)d_in[5];
    const float* wv_sa = (const float*)d_in[6];
    const float* wo_sa = (const float*)d_in[7];
    const float* wq_at = (const float*)d_in[8];
    const float* wk_at = (const float*)d_in[9];
    const float* wq_rl = (const float*)d_in[10];
    const float* wk_rl = (const float*)d_in[11];
    const float* wr    = (const float*)d_in[12];
    const float* wv_ra = (const float*)d_in[13];
    const float* wo_ra = (const float*)d_in[14];
    float* out = (float*)d_out;

    float *wcat, *proj, *sv, *sc_sa, *sc_ra, *rel, *ctx_sa, *ctx_ra, *attrel;
    cudaGetSymbolAddress((void**)&wcat,   g_wcat);
    cudaGetSymbolAddress((void**)&proj,   g_proj);
    cudaGetSymbolAddress((void**)&sv,     g_sv);
    cudaGetSymbolAddress((void**)&sc_sa,  g_sc_sa);
    cudaGetSymbolAddress((void**)&sc_ra,  g_sc_ra);
    cudaGetSymbolAddress((void**)&rel,    g_rel);
    cudaGetSymbolAddress((void**)&ctx_sa, g_ctx_sa);
    cudaGetSymbolAddress((void**)&ctx_ra, g_ctx_ra);
    cudaGetSymbolAddress((void**)&attrel, g_attrel);

    // streams/events created once, on the first (non-captured) correctness call
    static cudaStream_t s1 = nullptr, s2 = nullptr;
    static cudaEvent_t ev0, ev1, ev2, ev3, ev4;
    if (s1 == nullptr) {
        cudaStreamCreateWithFlags(&s1, cudaStreamNonBlocking);
        cudaStreamCreateWithFlags(&s2, cudaStreamNonBlocking);
        cudaEventCreateWithFlags(&ev0, cudaEventDisableTiming);
        cudaEventCreateWithFlags(&ev1, cudaEventDisableTiming);
        cudaEventCreateWithFlags(&ev2, cudaEventDisableTiming);
        cudaEventCreateWithFlags(&ev3, cudaEventDisableTiming);
        cudaEventCreateWithFlags(&ev4, cudaEventDisableTiming);
    }

    dim3 tpb(256);
    const float scl = 0.125f;                       // 1/sqrt(64)
    const long long bS  = (long long)SS * PLD;      // per-batch stride in proj
    const long long sHS = (long long)SS * SS;       // per-head score stride
    const long long sBS = (long long)HH * SS * SS;  // per-batch score stride

    // ---- fork
    cudaEventRecord(ev0, 0);
    cudaStreamWaitEvent(s1, ev0, 0);
    cudaStreamWaitEvent(s2, ev0, 0);

    // s1: sv = symbols @ wv_ra^T  (independent of x path)
    gemm_bf<128, true, false, false><<<dim3(4, 32, 1), tpb, 0, s1>>>(
        symb, DM, 0, 0, wv_ra, DM, 0, 0, sv, 512, 0, 0, MTOT, 512, DM, 1, 1.0f);

    // stream 0: fused input projections + RoPE
    copy_wcat_k<<<14336, 256>>>(wq_sa, wk_sa, wv_sa, wq_at, wk_at, wq_rl, wk_rl, wcat);
    gemm_bf<128, true, false, false><<<dim3(28, 32, 1), tpb>>>(
        x, DM, 0, 0, wcat, DM, 0, 0, proj, PLD, 0, 0, MTOT, PLD, DM, 1, 1.0f);
    rope_k<<<16384, 256>>>(proj, fc, fs);
    cudaEventRecord(ev1, 0);
    cudaStreamWaitEvent(s1, ev1, 0);
    cudaStreamWaitEvent(s2, ev1, 0);

    // score GEMMs concurrently on 3 streams
    gemm_bf<128, true, true, false><<<dim3(16, 16, 16), tpb>>>(
        proj + 0 * 512, PLD, bS, 64, proj + 1 * 512, PLD, bS, 64,
        sc_sa, SS, sBS, sHS, SS, SS, 64, HH, scl);
    gemm_bf<128, true, true, false><<<dim3(16, 16, 16), tpb, 0, s1>>>(
        proj + 3 * 512, PLD, bS, 64, proj + 4 * 512, PLD, bS, 64,
        sc_ra, SS, sBS, sHS, SS, SS, 64, HH, scl);
    gemm_bf<128, true, true, false><<<dim3(16, 16, 16), tpb, 0, s2>>>(
        proj + 5 * 512, PLD, bS, 64, proj + 6 * 512, PLD, bS, 64,
        rel, SS, (long long)NREL * SS * SS, sHS, SS, SS, 64, NREL, scl);

    // softmaxes
    softmax_k<<<dim3(SS, BB * HH), 256>>>(sc_sa);
    softmax_k<<<dim3(SS, BB * HH), 256, 0, s1>>>(sc_ra);
    cudaEventRecord(ev2, s1);                       // alpha_ra ready

    // ctx = alpha @ V, concurrent
    gemm_bf<64, false, false, true><<<dim3(1, 16, 16), tpb>>>(
        sc_sa, SS, sBS, sHS, proj + 2 * 512, PLD, bS, 64,
        ctx_sa, 512, (long long)SS * 512, 64, SS, 64, SS, HH, 1.0f);
    gemm_bf<64, false, false, true><<<dim3(1, 16, 16), tpb, 0, s1>>>(
        sc_ra, SS, sBS, sHS, sv, 512, (long long)SS * 512, 64,
        ctx_ra, 512, (long long)SS * 512, 64, SS, 64, SS, HH, 1.0f);
    cudaEventRecord(ev3, s1);                       // ctx_ra ready

    // s2: attrel (needs rel [s2 in-order] + alpha_ra), then relout (needs ctx_ra)
    cudaStreamWaitEvent(s2, ev2, 0);
    attrel_k<<<dim3(SS, BB), 256, 0, s2>>>(sc_ra, rel, attrel);
    cudaStreamWaitEvent(s2, ev3, 0);
    relout_k<<<8192, 256, 0, s2>>>(attrel, wr, ctx_ra);

    // output projections (SA on stream 0, RA on s2)
    gemm_bf<128, true, false, false><<<dim3(4, 32, 1), tpb>>>(
        ctx_sa, 512, 0, 0, wo_sa, 512, 0, 0, out, DM, 0, 0, MTOT, 512, 512, 1, 1.0f);
    gemm_bf<128, true, false, false><<<dim3(4, 32, 1), tpb, 0, s2>>>(
        ctx_ra, 512, 0, 0, wo_ra, 512, 0, 0, out + 512, DM, 0, 0, MTOT, 512, 512, 1, 1.0f);

    // ---- join
    cudaEventRecord(ev4, s2);
    cudaStreamWaitEvent(0, ev4, 0);
}

// round 16
// speedup vs baseline: 2.0369x; 1.0212x over previous
#include <cuda_runtime.h>
#include <cuda_bf16.h>
#include <cstdint>

#define BB 2
#define SS 2048
#define DM 1024
#define HH 8
#define HD 64
#define NREL 8
#define MTOT (BB*SS)          // 4096 rows (b,s flattened)
#define PLD 3584              // fused projection row stride (7*512)

// ---------------- scratch (device globals; no allocation allowed) ----------------
static __device__ float g_wcat[(size_t)7*512*DM];                 // 14 MB
static __device__ float g_proj[(size_t)MTOT*PLD];                 // 59 MB
static __device__ float g_sv[(size_t)MTOT*512];                   // 8.4 MB
static __device__ float g_sc_ra[(size_t)BB*HH*SS*SS];             // 268 MB
static __device__ float g_rel[(size_t)BB*NREL*SS*SS];             // 268 MB
static __device__ float g_ctx_sa[(size_t)MTOT*512];               // 8.4 MB
static __device__ float g_ctx_ra[(size_t)MTOT*512];               // 8.4 MB
static __device__ float g_attrel[(size_t)MTOT*64];                // 1 MB

// ---------------- common helpers ----------------
__device__ __forceinline__ void split2(float x, float y, uint32_t& hi, uint32_t& lo) {
    __nv_bfloat16 hx = __float2bfloat16_rn(x), hy = __float2bfloat16_rn(y);
    __nv_bfloat16 lx = __float2bfloat16_rn(x - __bfloat162float(hx));
    __nv_bfloat16 ly = __float2bfloat16_rn(y - __bfloat162float(hy));
    hi = (uint32_t)__bfloat16_as_ushort(hx) | ((uint32_t)__bfloat16_as_ushort(hy) << 16);
    lo = (uint32_t)__bfloat16_as_ushort(lx) | ((uint32_t)__bfloat16_as_ushort(ly) << 16);
}

__device__ __forceinline__ void mma_bf16(float* c, const uint32_t* a, const uint32_t* b) {
    asm volatile(
        "mma.sync.aligned.m16n8k16.row.col.f32.bf16.bf16.f32 "
        "{%0,%1,%2,%3}, {%4,%5,%6,%7}, {%8,%9}, {%0,%1,%2,%3};\n"
        : "+f"(c[0]), "+f"(c[1]), "+f"(c[2]), "+f"(c[3])
        : "r"(a[0]), "r"(a[1]), "r"(a[2]), "r"(a[3]), "r"(b[0]), "r"(b[1]));
}

// ==================================================================================
// bf16x3 tensor-core GEMM via mma.sync.m16n8k16 (unchanged workhorse).
// ==================================================================================
template<int BN_, bool TRANSB, bool CAUSAL, bool KCLAMP>
__global__ __launch_bounds__(256)
void gemm_bf(const float* __restrict__ A, int lda, long long sAo, long long sAi,
             const float* __restrict__ B, int ldb, long long sBo, long long sBi,
             float* __restrict__ C, int ldc, long long sCo, long long sCi,
             int M, int N, int K, int inner, float scale)
{
    constexpr int NT8 = BN_ / 8;
    constexpr int NT  = NT8 / 4;
    constexpr int ALD = 4;
    constexpr int BLD = BN_ / 32;
    constexpr int SB0 = 4096;
    static_assert(TRANSB || BN_ == 64, "NN loader assumes BN_==64");

    __shared__ uint32_t sm[4096 + NT8 * 256];

    int bx = blockIdx.x, by = blockIdx.y, bz = blockIdx.z;
    if (CAUSAL && bx > by) return;
    int outer = bz / inner, in = bz % inner;
    A += outer * sAo + (long long)in * sAi;
    B += outer * sBo + (long long)in * sBi;
    C += outer * sCo + (long long)in * sCi;
    int m0 = by * 128, n0 = bx * BN_;
    int kend = KCLAMP ? min(K, m0 + 128) : K;
    int nit = kend >> 5;

    int tid = threadIdx.x, wid = tid >> 5, lane = tid & 31;
    int wm = wid >> 2, wn = wid & 3;

    auto sAi_ = [](int h, int k16, int mt, int ln, int rg) {
        return (((h * 2 + k16) * 8 + mt) * 32 + ln) * 4 + rg;
    };
    auto sBi_ = [](int h, int k16, int bt, int ln, int rg) {
        return SB0 + (((h * 2 + k16) * NT8 + bt) * 32 + ln) * 2 + rg;
    };

    float c[4][NT][4];
#pragma unroll
    for (int i = 0; i < 4; i++)
#pragma unroll
        for (int j = 0; j < NT; j++)
#pragma unroll
            for (int r = 0; r < 4; r++) c[i][j][r] = 0.f;

    float4 rA[ALD];
    float4 rB[TRANSB ? BLD : 2];

    auto g2r = [&](int kt) {
        int k0 = kt << 5;
#pragma unroll
        for (int it = 0; it < ALD; it++) {
            int idx = tid + it * 256;
            int row = idx >> 3, kq = (idx & 7) << 2;
            rA[it] = *(const float4*)(A + (size_t)(m0 + row) * lda + k0 + kq);
        }
        if (TRANSB) {
#pragma unroll
            for (int it = 0; it < BLD; it++) {
                int idx = tid + it * 256;
                int n = idx >> 3, kq = (idx & 7) << 2;
                rB[it] = *(const float4*)(B + (size_t)(n0 + n) * ldb + k0 + kq);
            }
        } else {
            int n = tid & 63, kb = (tid >> 6) * 8;
            const float* Bb = B + (size_t)(k0 + kb) * ldb + n0 + n;
            float v[8];
#pragma unroll
            for (int kk = 0; kk < 8; kk++) v[kk] = Bb[(size_t)kk * ldb];
            rB[0] = make_float4(v[0], v[1], v[2], v[3]);
            rB[1] = make_float4(v[4], v[5], v[6], v[7]);
        }
    };

    auto sts = [&]() {
#pragma unroll
        for (int it = 0; it < ALD; it++) {
            int idx = tid + it * 256;
            int row = idx >> 3, kq = (idx & 7) << 2;
            int k16 = kq >> 4, kk0 = kq & 15;
            int mt = row >> 4, r = row & 15, g = r & 7, half = r >> 3;
            int t0 = (kk0 & 7) >> 1;
            int rb = half + ((kk0 & 8) ? 2 : 0);
            uint32_t h0, l0, h1, l1;
            split2(rA[it].x, rA[it].y, h0, l0);
            split2(rA[it].z, rA[it].w, h1, l1);
            int ln = g * 4 + t0;
            sm[sAi_(0, k16, mt, ln, rb)]     = h0;
            sm[sAi_(1, k16, mt, ln, rb)]     = l0;
            sm[sAi_(0, k16, mt, ln + 1, rb)] = h1;
            sm[sAi_(1, k16, mt, ln + 1, rb)] = l1;
        }
        if (TRANSB) {
#pragma unroll
            for (int it = 0; it < BLD; it++) {
                int idx = tid + it * 256;
                int n = idx >> 3, kq = (idx & 7) << 2;
                int k16 = kq >> 4, kk0 = kq & 15;
                int bt = n >> 3, g = n & 7;
                int t0 = (kk0 & 7) >> 1;
                int rb = (kk0 & 8) ? 1 : 0;
                uint32_t h0, l0, h1, l1;
                split2(rB[it].x, rB[it].y, h0, l0);
                split2(rB[it].z, rB[it].w, h1, l1);
                int ln = g * 4 + t0;
                sm[sBi_(0, k16, bt, ln, rb)]     = h0;
                sm[sBi_(1, k16, bt, ln, rb)]     = l0;
                sm[sBi_(0, k16, bt, ln + 1, rb)] = h1;
                sm[sBi_(1, k16, bt, ln + 1, rb)] = l1;
            }
        } else {
            int n = tid & 63, kb = (tid >> 6) * 8;
            int bt = n >> 3, g = n & 7;
            float v[8] = {rB[0].x, rB[0].y, rB[0].z, rB[0].w,
                          rB[1].x, rB[1].y, rB[1].z, rB[1].w};
#pragma unroll
            for (int kk2 = 0; kk2 < 8; kk2++) {
                int k = kb + kk2;
                int k16 = k >> 4, kk = k & 15;
                int t = (kk & 7) >> 1, e = kk & 1, rg = (kk & 8) ? 1 : 0;
                int ln = g * 4 + t;
                __nv_bfloat16 hv = __float2bfloat16_rn(v[kk2]);
                __nv_bfloat16 lv = __float2bfloat16_rn(v[kk2] - __bfloat162float(hv));
                ((__nv_bfloat16*)&sm[sBi_(0, k16, bt, ln, rg)])[e] = hv;
                ((__nv_bfloat16*)&sm[sBi_(1, k16, bt, ln, rg)])[e] = lv;
            }
        }
    };

    g2r(0);
    for (int kt = 0; kt < nit; kt++) {
        sts();
        __syncthreads();
        if (kt + 1 < nit) g2r(kt + 1);

#pragma unroll
        for (int k16 = 0; k16 < 2; k16++) {
            uint32_t ah[4][4], al[4][4], bh[NT][2], bl[NT][2];
#pragma unroll
            for (int i = 0; i < 4; i++) {
                *(uint4*)ah[i] = *(const uint4*)&sm[sAi_(0, k16, wm * 4 + i, lane, 0)];
                *(uint4*)al[i] = *(const uint4*)&sm[sAi_(1, k16, wm * 4 + i, lane, 0)];
            }
#pragma unroll
            for (int j = 0; j < NT; j++) {
                *(uint2*)bh[j] = *(const uint2*)&sm[sBi_(0, k16, wn * NT + j, lane, 0)];
                *(uint2*)bl[j] = *(const uint2*)&sm[sBi_(1, k16, wn * NT + j, lane, 0)];
            }
#pragma unroll
            for (int i = 0; i < 4; i++)
#pragma unroll
                for (int j = 0; j < NT; j++) {
                    mma_bf16(c[i][j], ah[i], bh[j]);
                    mma_bf16(c[i][j], ah[i], bl[j]);
                    mma_bf16(c[i][j], al[i], bh[j]);
                }
        }
        __syncthreads();
    }

    int g = lane >> 2, t = lane & 3;
#pragma unroll
    for (int i = 0; i < 4; i++)
#pragma unroll
        for (int j = 0; j < NT; j++) {
            int m = m0 + wm * 64 + i * 16 + g;
            int n = n0 + wn * (BN_ / 4) + j * 8 + t * 2;
            float2 v0 = {c[i][j][0] * scale, c[i][j][1] * scale};
            float2 v1 = {c[i][j][2] * scale, c[i][j][3] * scale};
            *(float2*)(C + (size_t)m * ldc + n) = v0;
            *(float2*)(C + (size_t)(m + 8) * ldc + n) = v1;
        }
}

// ==================================================================================
// Fused flash attention for the SA stream: score(bf16x3) + online softmax + P@V.
// grid (16 itile, 16 bh), 256 thr = 8 warps; warp w owns rows itile*128+w*16+{g,g+8}.
// Q frags in registers; K/V frags in 64KB dynamic smem per 128-wide KV block.
// S C-frags are reused directly as P A-frags (no smem round trip).
// ==================================================================================
__global__ __launch_bounds__(256, 1)
void flash_sa(const float* __restrict__ proj, float* __restrict__ ctx)
{
    extern __shared__ uint32_t sm[];   // [0,4096) Khi [4096,8192) Klo [8192,12288) Vhi [12288,16384) Vlo
    int itile = (int)gridDim.x - 1 - (int)blockIdx.x;   // longest CTAs first
    int bh = blockIdx.y;
    int b = bh >> 3, h = bh & 7;
    const float* pb = proj + (size_t)b * SS * PLD;
    const float* Qp = pb + h * 64;
    const float* Kp = pb + 512 + h * 64;
    const float* Vp = pb + 1024 + h * 64;

    int tid = threadIdx.x, w = tid >> 5, lane = tid & 31;
    int g = lane >> 2, t = lane & 3;
    int row0 = itile * 128 + w * 16 + g;           // rows row0, row0+8

    // ---- Q fragments in registers, pre-scaled by 1/8
    uint32_t qh[4][4], ql[4][4];
    {
        const float* r0 = Qp + (size_t)row0 * PLD;
        const float* r1 = Qp + (size_t)(row0 + 8) * PLD;
#pragma unroll
        for (int ks = 0; ks < 4; ks++) {
            float2 v0 = *(const float2*)(r0 + ks * 16 + 2 * t);
            float2 v1 = *(const float2*)(r1 + ks * 16 + 2 * t);
            float2 v2 = *(const float2*)(r0 + ks * 16 + 8 + 2 * t);
            float2 v3 = *(const float2*)(r1 + ks * 16 + 8 + 2 * t);
            split2(v0.x * 0.125f, v0.y * 0.125f, qh[ks][0], ql[ks][0]);
            split2(v1.x * 0.125f, v1.y * 0.125f, qh[ks][1], ql[ks][1]);
            split2(v2.x * 0.125f, v2.y * 0.125f, qh[ks][2], ql[ks][2]);
            split2(v3.x * 0.125f, v3.y * 0.125f, qh[ks][3], ql[ks][3]);
        }
    }

    float o[8][4];
#pragma unroll
    for (int nt = 0; nt < 8; nt++)
#pragma unroll
        for (int r = 0; r < 4; r++) o[nt][r] = 0.f;
    float m0 = -1e30f, m1 = -1e30f, l0 = 0.f, l1 = 0.f;

    for (int jb = 0; jb <= itile; jb++) {
        int j0 = jb * 128;
        __syncthreads();
        // ---- load K tile (128 j-rows x 64 d) into B-fragment order, hi/lo
#pragma unroll
        for (int it = 0; it < 8; it++) {
            int idx = tid + it * 256;
            int n = idx >> 4, kq = (idx & 15) * 4;
            float4 v = *(const float4*)(Kp + (size_t)(j0 + n) * PLD + kq);
            int k16 = kq >> 4, rb = (kq & 8) ? 1 : 0, tb = (kq & 7) >> 1;
            int nt = n >> 3, lnb = (n & 7) * 4;
            uint32_t hh0, ll0, hh1, ll1;
            split2(v.x, v.y, hh0, ll0);
            split2(v.z, v.w, hh1, ll1);
            int base = (k16 * 16 + nt) * 64 + (lnb + tb) * 2 + rb;
            sm[base] = hh0;  sm[base + 4096] = ll0;
            int base2 = base + 2;
            sm[base2] = hh1; sm[base2 + 4096] = ll1;
        }
        // ---- load V tile (128 j x 64 d) into B-fragment order (k=j, n=d), hi/lo
#pragma unroll
        for (int it = 0; it < 8; it++) {
            int idx = tid + it * 256;
            int j = idx >> 4, dq = (idx & 15) * 4;
            float4 v = *(const float4*)(Vp + (size_t)(j0 + j) * PLD + dq);
            int ks = j >> 4, kk = j & 15;
            int tb = (kk & 7) >> 1, e = kk & 1, rg = (kk & 8) ? 1 : 0;
            float vv[4] = {v.x, v.y, v.z, v.w};
#pragma unroll
            for (int q = 0; q < 4; q++) {
                int d = dq + q;
                int nt = d >> 3, gd = d & 7;
                int base = 8192 + (ks * 8 + nt) * 64 + (gd * 4 + tb) * 2 + rg;
                __nv_bfloat16 hv = __float2bfloat16_rn(vv[q]);
                __nv_bfloat16 lv = __float2bfloat16_rn(vv[q] - __bfloat162float(hv));
                ((__nv_bfloat16*)&sm[base])[e] = hv;
                ((__nv_bfloat16*)&sm[base + 4096])[e] = lv;
            }
        }
        __syncthreads();

        // ---- S = Q K^T (bf16x3), 16 rows x 128 cols per warp
        float s[16][4];
#pragma unroll
        for (int nt = 0; nt < 16; nt++)
#pragma unroll
            for (int r = 0; r < 4; r++) s[nt][r] = 0.f;
#pragma unroll
        for (int ks = 0; ks < 4; ks++)
#pragma unroll
            for (int nt = 0; nt < 16; nt++) {
                uint32_t kb_[2], kl_[2];
                *(uint2*)kb_ = *(const uint2*)&sm[(ks * 16 + nt) * 64 + lane * 2];
                *(uint2*)kl_ = *(const uint2*)&sm[4096 + (ks * 16 + nt) * 64 + lane * 2];
                mma_bf16(s[nt], qh[ks], kb_);
                mma_bf16(s[nt], qh[ks], kl_);
                mma_bf16(s[nt], ql[ks], kb_);
            }

        // ---- causal mask (diagonal block only)
        if (jb == itile) {
#pragma unroll
            for (int nt = 0; nt < 16; nt++) {
                int col = j0 + nt * 8 + 2 * t;
                if (col > row0)         s[nt][0] = -1e30f;
                if (col + 1 > row0)     s[nt][1] = -1e30f;
                if (col > row0 + 8)     s[nt][2] = -1e30f;
                if (col + 1 > row0 + 8) s[nt][3] = -1e30f;
            }
        }

        // ---- online softmax (rows fully within warp; quad shuffles over t)
        float bm0 = -1e30f, bm1 = -1e30f;
#pragma unroll
        for (int nt = 0; nt < 16; nt++) {
            bm0 = fmaxf(bm0, fmaxf(s[nt][0], s[nt][1]));
            bm1 = fmaxf(bm1, fmaxf(s[nt][2], s[nt][3]));
        }
        bm0 = fmaxf(bm0, __shfl_xor_sync(0xffffffffu, bm0, 1));
        bm0 = fmaxf(bm0, __shfl_xor_sync(0xffffffffu, bm0, 2));
        bm1 = fmaxf(bm1, __shfl_xor_sync(0xffffffffu, bm1, 1));
        bm1 = fmaxf(bm1, __shfl_xor_sync(0xffffffffu, bm1, 2));
        float nm0 = fmaxf(m0, bm0), nm1 = fmaxf(m1, bm1);
        float sc0 = __expf(m0 - nm0), sc1 = __expf(m1 - nm1);
        float rs0 = 0.f, rs1 = 0.f;
#pragma unroll
        for (int nt = 0; nt < 16; nt++) {
            s[nt][0] = __expf(s[nt][0] - nm0); rs0 += s[nt][0];
            s[nt][1] = __expf(s[nt][1] - nm0); rs0 += s[nt][1];
            s[nt][2] = __expf(s[nt][2] - nm1); rs1 += s[nt][2];
            s[nt][3] = __expf(s[nt][3] - nm1); rs1 += s[nt][3];
        }
        rs0 += __shfl_xor_sync(0xffffffffu, rs0, 1);
        rs0 += __shfl_xor_sync(0xffffffffu, rs0, 2);
        rs1 += __shfl_xor_sync(0xffffffffu, rs1, 1);
        rs1 += __shfl_xor_sync(0xffffffffu, rs1, 2);
        l0 = l0 * sc0 + rs0;  l1 = l1 * sc1 + rs1;
        m0 = nm0;  m1 = nm1;
#pragma unroll
        for (int nt = 0; nt < 8; nt++) {
            o[nt][0] *= sc0; o[nt][1] *= sc0;
            o[nt][2] *= sc1; o[nt][3] *= sc1;
        }

        // ---- O += P V  (P A-frags straight from S C-frags, bf16x3)
#pragma unroll
        for (int ks = 0; ks < 8; ks++) {
            uint32_t ah[4], al[4];
            split2(s[2 * ks][0],     s[2 * ks][1],     ah[0], al[0]);
            split2(s[2 * ks][2],     s[2 * ks][3],     ah[1], al[1]);
            split2(s[2 * ks + 1][0], s[2 * ks + 1][1], ah[2], al[2]);
            split2(s[2 * ks + 1][2], s[2 * ks + 1][3], ah[3], al[3]);
#pragma unroll
            for (int nt = 0; nt < 8; nt++) {
                uint32_t vh_[2], vl_[2];
                *(uint2*)vh_ = *(const uint2*)&sm[8192 + (ks * 8 + nt) * 64 + lane * 2];
                *(uint2*)vl_ = *(const uint2*)&sm[12288 + (ks * 8 + nt) * 64 + lane * 2];
                mma_bf16(o[nt], ah, vh_);
                mma_bf16(o[nt], al, vh_);
                mma_bf16(o[nt], ah, vl_);
            }
        }
    }

    // ---- normalize + store ctx tile (row-major (MTOT, 512), col h*64+d)
    float i0v = 1.f / l0, i1v = 1.f / l1;
    float* cr0 = ctx + ((size_t)b * SS + row0) * 512 + h * 64;
    float* cr1 = cr0 + (size_t)8 * 512;
#pragma unroll
    for (int nt = 0; nt < 8; nt++) {
        float2 a = {o[nt][0] * i0v, o[nt][1] * i0v};
        float2 c2 = {o[nt][2] * i1v, o[nt][3] * i1v};
        *(float2*)(cr0 + nt * 8 + 2 * t) = a;
        *(float2*)(cr1 + nt * 8 + 2 * t) = c2;
    }
}

// ---------------- weight concat: 7 x (512,1024) -> g_wcat (3584,1024) ----------------
__global__ void copy_wcat_k(const float* __restrict__ w0, const float* __restrict__ w1,
                            const float* __restrict__ w2, const float* __restrict__ w3,
                            const float* __restrict__ w4, const float* __restrict__ w5,
                            const float* __restrict__ w6, float* __restrict__ dst)
{
    size_t idx = (size_t)blockIdx.x * blockDim.x + threadIdx.x;
    const size_t per = (size_t)512 * DM;
    if (idx >= 7 * per) return;
    int p = (int)(idx / per);
    size_t off = idx % per;
    const float* w = w0;
    if (p == 1) w = w1; else if (p == 2) w = w2; else if (p == 3) w = w3;
    else if (p == 4) w = w4; else if (p == 5) w = w5; else if (p == 6) w = w6;
    dst[idx] = w[off];
}

// ---------------- RoPE on slabs {0:q_sa, 1:k_sa, 3:qa, 4:ka} of g_proj ----------------
__global__ void rope_k(float* __restrict__ proj, const float* __restrict__ fc,
                       const float* __restrict__ fs)
{
    size_t idx = (size_t)blockIdx.x * blockDim.x + threadIdx.x;
    int m = idx & 31;
    int h = (idx >> 5) & 7;
    int p = (idx >> 8) & 3;
    size_t row = idx >> 10;
    if (row >= (size_t)MTOT) return;
    int s = (int)(row & (SS - 1));
    int pc = (p < 2) ? p : p + 1;     // {0,1,3,4}
    float* base = proj + row * PLD + pc * 512 + h * 64 + 2 * m;
    float c = fc[s * 32 + m];
    float sn = fs[s * 32 + m];
    float xr = base[0], xi = base[1];
    base[0] = xr * c - xi * sn;
    base[1] = xr * sn + xi * c;
}

// ---------------- causal band softmax: reads and writes only j < band end ----------------
__global__ void softmax_k(float* __restrict__ sc)
{
    int i = blockIdx.x;
    long long g = blockIdx.y;
    float* row = sc + (g * SS + (long long)i) * SS;
    int t = threadIdx.x;
    int wlim = ((i >> 7) + 1) << 7;       // causal band end (multiple of 128)
    const int C = SS / 256;
    float vals[C];
    float mx = -3.4e38f;
#pragma unroll
    for (int c = 0; c < C; c++) {
        int j = t + c * 256;
        float v = -3.4e38f;
        if (j < wlim && j <= i) v = row[j];
        vals[c] = v;
        mx = fmaxf(mx, v);
    }
    __shared__ float red[256];
    red[t] = mx; __syncthreads();
    for (int o = 128; o > 0; o >>= 1) { if (t < o) red[t] = fmaxf(red[t], red[t + o]); __syncthreads(); }
    mx = red[0];
    __syncthreads();
    float sum = 0.f;
#pragma unroll
    for (int c = 0; c < C; c++) {
        float e = __expf(vals[c] - mx);
        vals[c] = e;
        sum += e;
    }
    red[t] = sum; __syncthreads();
    for (int o = 128; o > 0; o >>= 1) { if (t < o) red[t] += red[t + o]; __syncthreads(); }
    float inv = 1.0f / red[0];
#pragma unroll
    for (int c = 0; c < C; c++) {
        int j = t + c * 256;
        if (j < wlim) row[j] = vals[c] * inv;
    }
}

// ---------------- attended_rel v2: coalesced, smem-staged ----------------
// attended_rel[b,i,h,r] = sum_{j<=i} alpha[b,h,i,j] * rel[b,r,i,j]
__global__ void attrel_k2(const float* __restrict__ alpha, const float* __restrict__ rel,
                          float* __restrict__ out)
{
    int i = blockIdx.x, b = blockIdx.y;
    int t = threadIdx.x;
    __shared__ float sA[8][256], sR[8][256];
    __shared__ float red[256];
    int o = t & 63, sl = t >> 6;          // o = h*8+r, slice 0..3
    int h = o >> 3, r = o & 7;
    float acc = 0.f;
    for (int j0 = 0; j0 <= i; j0 += 256) {
        __syncthreads();
        for (int k = t; k < 2048; k += 256) {
            int row = k >> 8, col = k & 255;
            int j = j0 + col;
            float av = 0.f, rv = 0.f;
            if (j <= i) {
                av = alpha[((size_t)(b * 8 + row) * SS + i) * SS + j];
                rv = rel[((size_t)(b * 8 + row) * SS + i) * SS + j];
            }
            sA[row][col] = av;
            sR[row][col] = rv;
        }
        __syncthreads();
        const float* pa = &sA[h][sl * 64];
        const float* pr = &sR[r][sl * 64];
#pragma unroll 8
        for (int c = 0; c < 64; c++) acc += pa[c] * pr[c];
    }
    red[t] = acc;
    __syncthreads();
    if (t < 64)
        out[((size_t)b * SS + i) * 64 + t] = red[t] + red[t + 64] + red[t + 128] + red[t + 192];
}

// ---------------- ctx_ra += einsum('bihr,hdr->bihd', attrel, wr) ----------------
__global__ void relout_k(const float* __restrict__ attrel, const float* __restrict__ wr,
                         float* __restrict__ ctx)
{
    size_t idx = (size_t)blockIdx.x * blockDim.x + threadIdx.x;
    if (idx >= (size_t)MTOT * 512) return;
    int d = idx & 63;
    int h = (idx >> 6) & 7;
    size_t bi = idx >> 9;
    const float* ar = attrel + bi * 64 + h * 8;
    const float* w = wr + ((size_t)h * 64 + d) * 8;
    float v = 0.f;
#pragma unroll
    for (int r = 0; r < 8; r++) v += ar[r] * w[r];
    ctx[idx] += v;
}

// ---------------- launcher (multi-stream fork/join, graph-capture safe) ----------------
extern "C" void kernel_launch(void* const* d_in, const int* in_sizes, int n_in,
                              void* d_out, int out_size)
{
    const float* x     = (const float*)d_in[0];
    const float* symb  = (const float*)d_in[1];
    const float* fc    = (const float*)d_in[2];
    const float* fs    = (const float*)d_in[3];
    const float* wq_sa = (const float*)d_in[4];
    const float* wk_sa = (const float*)d_in[5];
    const float* wv_sa = (const float*)d_in[6];
    const float* wo_sa = (const float*)d_in[7];
    const float* wq_at = (const float*)d_in[8];
    const float* wk_at = (const float*)d_in[9];
    const float* wq_rl = (const float*)d_in[10];
    const float* wk_rl = (const float*)d_in[11];
    const float* wr    = (const float*)d_in[12];
    const float* wv_ra = (const float*)d_in[13];
    const float* wo_ra = (const float*)d_in[14];
    float* out = (float*)d_out;

    float *wcat, *proj, *sv, *sc_ra, *rel, *ctx_sa, *ctx_ra, *attrel;
    cudaGetSymbolAddress((void**)&wcat,   g_wcat);
    cudaGetSymbolAddress((void**)&proj,   g_proj);
    cudaGetSymbolAddress((void**)&sv,     g_sv);
    cudaGetSymbolAddress((void**)&sc_ra,  g_sc_ra);
    cudaGetSymbolAddress((void**)&rel,    g_rel);
    cudaGetSymbolAddress((void**)&ctx_sa, g_ctx_sa);
    cudaGetSymbolAddress((void**)&ctx_ra, g_ctx_ra);
    cudaGetSymbolAddress((void**)&attrel, g_attrel);

    // streams/events/attrs set once, on the first (non-captured) correctness call
    static cudaStream_t s1 = nullptr, s2 = nullptr;
    static cudaEvent_t ev0, ev1, ev2, ev3, ev4;
    if (s1 == nullptr) {
        cudaStreamCreateWithFlags(&s1, cudaStreamNonBlocking);
        cudaStreamCreateWithFlags(&s2, cudaStreamNonBlocking);
        cudaEventCreateWithFlags(&ev0, cudaEventDisableTiming);
        cudaEventCreateWithFlags(&ev1, cudaEventDisableTiming);
        cudaEventCreateWithFlags(&ev2, cudaEventDisableTiming);
        cudaEventCreateWithFlags(&ev3, cudaEventDisableTiming);
        cudaEventCreateWithFlags(&ev4, cudaEventDisableTiming);
        cudaFuncSetAttribute(flash_sa, cudaFuncAttributeMaxDynamicSharedMemorySize, 65536);
    }

    dim3 tpb(256);
    const float scl = 0.125f;                       // 1/sqrt(64)
    const long long bS  = (long long)SS * PLD;      // per-batch stride in proj
    const long long sHS = (long long)SS * SS;       // per-head score stride
    const long long sBS = (long long)HH * SS * SS;  // per-batch score stride

    // ---- fork
    cudaEventRecord(ev0, 0);
    cudaStreamWaitEvent(s1, ev0, 0);
    cudaStreamWaitEvent(s2, ev0, 0);

    // s1: sv = symbols @ wv_ra^T  (independent of x path)
    gemm_bf<128, true, false, false><<<dim3(4, 32, 1), tpb, 0, s1>>>(
        symb, DM, 0, 0, wv_ra, DM, 0, 0, sv, 512, 0, 0, MTOT, 512, DM, 1, 1.0f);

    // stream 0: fused input projections + RoPE
    copy_wcat_k<<<14336, 256>>>(wq_sa, wk_sa, wv_sa, wq_at, wk_at, wq_rl, wk_rl, wcat);
    gemm_bf<128, true, false, false><<<dim3(28, 32, 1), tpb>>>(
        x, DM, 0, 0, wcat, DM, 0, 0, proj, PLD, 0, 0, MTOT, PLD, DM, 1, 1.0f);
    rope_k<<<16384, 256>>>(proj, fc, fs);
    cudaEventRecord(ev1, 0);
    cudaStreamWaitEvent(s1, ev1, 0);
    cudaStreamWaitEvent(s2, ev1, 0);

    // stream 0: SA fused flash attention -> ctx_sa, then SA output projection
    flash_sa<<<dim3(16, 16), tpb, 65536>>>(proj, ctx_sa);
    gemm_bf<128, true, false, false><<<dim3(4, 32, 1), tpb>>>(
        ctx_sa, 512, 0, 0, wo_sa, 512, 0, 0, out, DM, 0, 0, MTOT, 512, 512, 1, 1.0f);

    // s1: RA scores -> band softmax -> alpha @ sv
    gemm_bf<128, true, true, false><<<dim3(16, 16, 16), tpb, 0, s1>>>(
        proj + 3 * 512, PLD, bS, 64, proj + 4 * 512, PLD, bS, 64,
        sc_ra, SS, sBS, sHS, SS, SS, 64, HH, scl);
    softmax_k<<<dim3(SS, BB * HH), 256, 0, s1>>>(sc_ra);
    cudaEventRecord(ev2, s1);                       // alpha_ra ready
    gemm_bf<64, false, false, true><<<dim3(1, 16, 16), tpb, 0, s1>>>(
        sc_ra, SS, sBS, sHS, sv, 512, (long long)SS * 512, 64,
        ctx_ra, 512, (long long)SS * 512, 64, SS, 64, SS, HH, 1.0f);
    cudaEventRecord(ev3, s1);                       // ctx_ra ready

    // s2: rel GEMM; attrel (needs rel + alpha_ra); relout (needs ctx_ra); RA out proj
    gemm_bf<128, true, true, false><<<dim3(16, 16, 16), tpb, 0, s2>>>(
        proj + 5 * 512, PLD, bS, 64, proj + 6 * 512, PLD, bS, 64,
        rel, SS, (long long)NREL * SS * SS, sHS, SS, SS, 64, NREL, scl);
    cudaStreamWaitEvent(s2, ev2, 0);
    attrel_k2<<<dim3(SS, BB), 256, 0, s2>>>(sc_ra, rel, attrel);
    cudaStreamWaitEvent(s2, ev3, 0);
    relout_k<<<8192, 256, 0, s2>>>(attrel, wr, ctx_ra);
    gemm_bf<128, true, false, false><<<dim3(4, 32, 1), tpb, 0, s2>>>(
        ctx_ra, 512, 0, 0, wo_ra, 512, 0, 0, out + 512, DM, 0, 0, MTOT, 512, 512, 1, 1.0f);

    // ---- join
    cudaEventRecord(ev4, s2);
    cudaStreamWaitEvent(0, ev4, 0);
}

// round 17
// speedup vs baseline: 2.8484x; 1.3984x over previous
#include <cuda_runtime.h>
#include <cuda_fp16.h>
#include <cstdint>

#define BB 2
#define SS 2048
#define DM 1024
#define HH 8
#define HD 64
#define NREL 8
#define MTOT (BB*SS)          // 4096 rows (b,s flattened)
#define PLD 3584              // fused projection row stride (7*512)

// ---------------- scratch (device globals; no allocation allowed) ----------------
static __device__ float g_wcat[(size_t)7*512*DM];                 // 14 MB
static __device__ float g_proj[(size_t)MTOT*PLD];                 // 59 MB
static __device__ float g_sv[(size_t)MTOT*512];                   // 8.4 MB
static __device__ float g_sc_ra[(size_t)BB*HH*SS*SS];             // 268 MB
static __device__ float g_rel[(size_t)BB*NREL*SS*SS];             // 268 MB
static __device__ float g_ctx_sa[(size_t)MTOT*512];               // 8.4 MB
static __device__ float g_ctx_ra[(size_t)MTOT*512];               // 8.4 MB
static __device__ float g_attrel[(size_t)MTOT*64];                // 1 MB

// ---------------- helpers ----------------
__device__ __forceinline__ uint32_t packh2(float x, float y) {
    __half2 h = __floats2half2_rn(x, y);
    return *(uint32_t*)&h;
}

__device__ __forceinline__ void mma_f16(float* c, const uint32_t* a, const uint32_t* b) {
    asm volatile(
        "mma.sync.aligned.m16n8k16.row.col.f32.f16.f16.f32 "
        "{%0,%1,%2,%3}, {%4,%5,%6,%7}, {%8,%9}, {%0,%1,%2,%3};\n"
        : "+f"(c[0]), "+f"(c[1]), "+f"(c[2]), "+f"(c[3])
        : "r"(a[0]), "r"(a[1]), "r"(a[2]), "r"(a[3]), "r"(b[0]), "r"(b[1]));
}

// ==================================================================================
// fp16x1 tensor-core GEMM via mma.sync.m16n8k16.
//   C = scale * A(M,K) * op(B), fp32 in/out, fp16 operands, fp32 accumulation.
// Tile: BM=128 x BN_ x BK=32. 256 thr = 8 warps (2x4), warptile 64 x BN_/4.
// Fragment-ordered smem: per-lane A frag = 1 LDS.128, B frag = 1 LDS.64.
// TRANSB=true : B is (N,K) row-major.  TRANSB=false: B is (K,N) row-major (BN_=64).
// CAUSAL: skip tiles above diagonal. KCLAMP: K limited to m0+128.
// ==================================================================================
template<int BN_, bool TRANSB, bool CAUSAL, bool KCLAMP>
__global__ __launch_bounds__(256)
void gemm_f16(const float* __restrict__ A, int lda, long long sAo, long long sAi,
              const float* __restrict__ B, int ldb, long long sBo, long long sBi,
              float* __restrict__ C, int ldc, long long sCo, long long sCi,
              int M, int N, int K, int inner, float scale)
{
    constexpr int NT8 = BN_ / 8;
    constexpr int NT  = NT8 / 4;
    constexpr int ALD = 4;
    constexpr int BLD = BN_ / 32;
    constexpr int SB0 = 2048;               // u32 offset of B region
    static_assert(TRANSB || BN_ == 64, "NN loader assumes BN_==64");

    __shared__ uint32_t sm[2048 + NT8 * 128];

    int bx = blockIdx.x, by = blockIdx.y, bz = blockIdx.z;
    if (CAUSAL && bx > by) return;
    int outer = bz / inner, in = bz % inner;
    A += outer * sAo + (long long)in * sAi;
    B += outer * sBo + (long long)in * sBi;
    C += outer * sCo + (long long)in * sCi;
    int m0 = by * 128, n0 = bx * BN_;
    int kend = KCLAMP ? min(K, m0 + 128) : K;
    int nit = kend >> 5;

    int tid = threadIdx.x, wid = tid >> 5, lane = tid & 31;
    int wm = wid >> 2, wn = wid & 3;

    auto sAi_ = [](int k16, int mt, int ln, int rg) {
        return ((k16 * 8 + mt) * 32 + ln) * 4 + rg;
    };
    auto sBi_ = [](int k16, int bt, int ln, int rg) {
        return SB0 + ((k16 * NT8 + bt) * 32 + ln) * 2 + rg;
    };

    float c[4][NT][4];
#pragma unroll
    for (int i = 0; i < 4; i++)
#pragma unroll
        for (int j = 0; j < NT; j++)
#pragma unroll
            for (int r = 0; r < 4; r++) c[i][j][r] = 0.f;

    float4 rA[ALD];
    float4 rB[TRANSB ? BLD : 2];

    auto g2r = [&](int kt) {
        int k0 = kt << 5;
#pragma unroll
        for (int it = 0; it < ALD; it++) {
            int idx = tid + it * 256;
            int row = idx >> 3, kq = (idx & 7) << 2;
            rA[it] = *(const float4*)(A + (size_t)(m0 + row) * lda + k0 + kq);
        }
        if (TRANSB) {
#pragma unroll
            for (int it = 0; it < BLD; it++) {
                int idx = tid + it * 256;
                int n = idx >> 3, kq = (idx & 7) << 2;
                rB[it] = *(const float4*)(B + (size_t)(n0 + n) * ldb + k0 + kq);
            }
        } else {
            int n = tid & 63, kb = (tid >> 6) * 8;
            const float* Bb = B + (size_t)(k0 + kb) * ldb + n0 + n;
            float v[8];
#pragma unroll
            for (int kk = 0; kk < 8; kk++) v[kk] = Bb[(size_t)kk * ldb];
            rB[0] = make_float4(v[0], v[1], v[2], v[3]);
            rB[1] = make_float4(v[4], v[5], v[6], v[7]);
        }
    };

    auto sts = [&]() {
#pragma unroll
        for (int it = 0; it < ALD; it++) {
            int idx = tid + it * 256;
            int row = idx >> 3, kq = (idx & 7) << 2;
            int k16 = kq >> 4, kk0 = kq & 15;
            int mt = row >> 4, r = row & 15, g = r & 7, half = r >> 3;
            int t0 = (kk0 & 7) >> 1;
            int rb = half + ((kk0 & 8) ? 2 : 0);
            int ln = g * 4 + t0;
            sm[sAi_(k16, mt, ln, rb)]     = packh2(rA[it].x, rA[it].y);
            sm[sAi_(k16, mt, ln + 1, rb)] = packh2(rA[it].z, rA[it].w);
        }
        if (TRANSB) {
#pragma unroll
            for (int it = 0; it < BLD; it++) {
                int idx = tid + it * 256;
                int n = idx >> 3, kq = (idx & 7) << 2;
                int k16 = kq >> 4, kk0 = kq & 15;
                int bt = n >> 3, g = n & 7;
                int t0 = (kk0 & 7) >> 1;
                int rb = (kk0 & 8) ? 1 : 0;
                int ln = g * 4 + t0;
                sm[sBi_(k16, bt, ln, rb)]     = packh2(rB[it].x, rB[it].y);
                sm[sBi_(k16, bt, ln + 1, rb)] = packh2(rB[it].z, rB[it].w);
            }
        } else {
            int n = tid & 63, kb = (tid >> 6) * 8;
            int bt = n >> 3, g = n & 7;
            float v[8] = {rB[0].x, rB[0].y, rB[0].z, rB[0].w,
                          rB[1].x, rB[1].y, rB[1].z, rB[1].w};
#pragma unroll
            for (int kk2 = 0; kk2 < 8; kk2++) {
                int k = kb + kk2;
                int k16 = k >> 4, kk = k & 15;
                int t = (kk & 7) >> 1, e = kk & 1, rg = (kk & 8) ? 1 : 0;
                int ln = g * 4 + t;
                ((__half*)&sm[sBi_(k16, bt, ln, rg)])[e] = __float2half_rn(v[kk2]);
            }
        }
    };

    g2r(0);
    for (int kt = 0; kt < nit; kt++) {
        sts();
        __syncthreads();
        if (kt + 1 < nit) g2r(kt + 1);

#pragma unroll
        for (int k16 = 0; k16 < 2; k16++) {
            uint32_t ah[4][4], bh[NT][2];
#pragma unroll
            for (int i = 0; i < 4; i++)
                *(uint4*)ah[i] = *(const uint4*)&sm[sAi_(k16, wm * 4 + i, lane, 0)];
#pragma unroll
            for (int j = 0; j < NT; j++)
                *(uint2*)bh[j] = *(const uint2*)&sm[sBi_(k16, wn * NT + j, lane, 0)];
#pragma unroll
            for (int i = 0; i < 4; i++)
#pragma unroll
                for (int j = 0; j < NT; j++)
                    mma_f16(c[i][j], ah[i], bh[j]);
        }
        __syncthreads();
    }

    int g = lane >> 2, t = lane & 3;
#pragma unroll
    for (int i = 0; i < 4; i++)
#pragma unroll
        for (int j = 0; j < NT; j++) {
            int m = m0 + wm * 64 + i * 16 + g;
            int n = n0 + wn * (BN_ / 4) + j * 8 + t * 2;
            float2 v0 = {c[i][j][0] * scale, c[i][j][1] * scale};
            float2 v1 = {c[i][j][2] * scale, c[i][j][3] * scale};
            *(float2*)(C + (size_t)m * ldc + n) = v0;
            *(float2*)(C + (size_t)(m + 8) * ldc + n) = v1;
        }
}

// ==================================================================================
// Fused flash attention (SA stream), fp16x1: QK^T + online softmax + P@V.
// grid (16 itile, 16 bh), 256 thr = 8 warps; warp w owns rows itile*128+w*16+{g,g+8}.
// ==================================================================================
__global__ __launch_bounds__(256)
void flash_sa(const float* __restrict__ proj, float* __restrict__ ctx)
{
    __shared__ uint32_t sm[8192];      // [0,4096) K frags, [4096,8192) V frags
    int itile = (int)gridDim.x - 1 - (int)blockIdx.x;   // longest CTAs first
    int bh = blockIdx.y;
    int b = bh >> 3, h = bh & 7;
    const float* pb = proj + (size_t)b * SS * PLD;
    const float* Qp = pb + h * 64;
    const float* Kp = pb + 512 + h * 64;
    const float* Vp = pb + 1024 + h * 64;

    int tid = threadIdx.x, w = tid >> 5, lane = tid & 31;
    int g = lane >> 2, t = lane & 3;
    int row0 = itile * 128 + w * 16 + g;           // rows row0, row0+8

    // ---- Q fragments (fp16), pre-scaled by 1/8
    uint32_t qh[4][4];
    {
        const float* r0 = Qp + (size_t)row0 * PLD;
        const float* r1 = Qp + (size_t)(row0 + 8) * PLD;
#pragma unroll
        for (int ks = 0; ks < 4; ks++) {
            float2 v0 = *(const float2*)(r0 + ks * 16 + 2 * t);
            float2 v1 = *(const float2*)(r1 + ks * 16 + 2 * t);
            float2 v2 = *(const float2*)(r0 + ks * 16 + 8 + 2 * t);
            float2 v3 = *(const float2*)(r1 + ks * 16 + 8 + 2 * t);
            qh[ks][0] = packh2(v0.x * 0.125f, v0.y * 0.125f);
            qh[ks][1] = packh2(v1.x * 0.125f, v1.y * 0.125f);
            qh[ks][2] = packh2(v2.x * 0.125f, v2.y * 0.125f);
            qh[ks][3] = packh2(v3.x * 0.125f, v3.y * 0.125f);
        }
    }

    float o[8][4];
#pragma unroll
    for (int nt = 0; nt < 8; nt++)
#pragma unroll
        for (int r = 0; r < 4; r++) o[nt][r] = 0.f;
    float m0 = -1e30f, m1 = -1e30f, l0 = 0.f, l1 = 0.f;

    for (int jb = 0; jb <= itile; jb++) {
        int j0 = jb * 128;
        __syncthreads();
        // ---- K tile (128 n x 64 d) into B-frag order
#pragma unroll
        for (int it = 0; it < 8; it++) {
            int idx = tid + it * 256;
            int n = idx >> 4, kq = (idx & 15) * 4;
            float4 v = *(const float4*)(Kp + (size_t)(j0 + n) * PLD + kq);
            int k16 = kq >> 4, rb = (kq & 8) ? 1 : 0, tb = (kq & 7) >> 1;
            int nt = n >> 3, lnb = (n & 7) * 4;
            int base = (k16 * 16 + nt) * 64 + (lnb + tb) * 2 + rb;
            sm[base]     = packh2(v.x, v.y);
            sm[base + 2] = packh2(v.z, v.w);
        }
        // ---- V tile (128 j x 64 d) into B-frag order (k=j, n=d)
#pragma unroll
        for (int it = 0; it < 8; it++) {
            int idx = tid + it * 256;
            int j = idx >> 4, dq = (idx & 15) * 4;
            float4 v = *(const float4*)(Vp + (size_t)(j0 + j) * PLD + dq);
            int ks = j >> 4, kk = j & 15;
            int tb = (kk & 7) >> 1, e = kk & 1, rg = (kk & 8) ? 1 : 0;
            float vv[4] = {v.x, v.y, v.z, v.w};
#pragma unroll
            for (int q = 0; q < 4; q++) {
                int d = dq + q;
                int nt = d >> 3, gd = d & 7;
                int base = 4096 + (ks * 8 + nt) * 64 + (gd * 4 + tb) * 2 + rg;
                ((__half*)&sm[base])[e] = __float2half_rn(vv[q]);
            }
        }
        __syncthreads();

        // ---- S = Q K^T
        float s[16][4];
#pragma unroll
        for (int nt = 0; nt < 16; nt++)
#pragma unroll
            for (int r = 0; r < 4; r++) s[nt][r] = 0.f;
#pragma unroll
        for (int ks = 0; ks < 4; ks++)
#pragma unroll
            for (int nt = 0; nt < 16; nt++) {
                uint32_t kb_[2];
                *(uint2*)kb_ = *(const uint2*)&sm[(ks * 16 + nt) * 64 + lane * 2];
                mma_f16(s[nt], qh[ks], kb_);
            }

        // ---- causal mask (diagonal block only)
        if (jb == itile) {
#pragma unroll
            for (int nt = 0; nt < 16; nt++) {
                int col = j0 + nt * 8 + 2 * t;
                if (col > row0)         s[nt][0] = -1e30f;
                if (col + 1 > row0)     s[nt][1] = -1e30f;
                if (col > row0 + 8)     s[nt][2] = -1e30f;
                if (col + 1 > row0 + 8) s[nt][3] = -1e30f;
            }
        }

        // ---- online softmax (quad shuffles over t)
        float bm0 = -1e30f, bm1 = -1e30f;
#pragma unroll
        for (int nt = 0; nt < 16; nt++) {
            bm0 = fmaxf(bm0, fmaxf(s[nt][0], s[nt][1]));
            bm1 = fmaxf(bm1, fmaxf(s[nt][2], s[nt][3]));
        }
        bm0 = fmaxf(bm0, __shfl_xor_sync(0xffffffffu, bm0, 1));
        bm0 = fmaxf(bm0, __shfl_xor_sync(0xffffffffu, bm0, 2));
        bm1 = fmaxf(bm1, __shfl_xor_sync(0xffffffffu, bm1, 1));
        bm1 = fmaxf(bm1, __shfl_xor_sync(0xffffffffu, bm1, 2));
        float nm0 = fmaxf(m0, bm0), nm1 = fmaxf(m1, bm1);
        float sc0 = __expf(m0 - nm0), sc1 = __expf(m1 - nm1);
        float rs0 = 0.f, rs1 = 0.f;
#pragma unroll
        for (int nt = 0; nt < 16; nt++) {
            s[nt][0] = __expf(s[nt][0] - nm0); rs0 += s[nt][0];
            s[nt][1] = __expf(s[nt][1] - nm0); rs0 += s[nt][1];
            s[nt][2] = __expf(s[nt][2] - nm1); rs1 += s[nt][2];
            s[nt][3] = __expf(s[nt][3] - nm1); rs1 += s[nt][3];
        }
        rs0 += __shfl_xor_sync(0xffffffffu, rs0, 1);
        rs0 += __shfl_xor_sync(0xffffffffu, rs0, 2);
        rs1 += __shfl_xor_sync(0xffffffffu, rs1, 1);
        rs1 += __shfl_xor_sync(0xffffffffu, rs1, 2);
        l0 = l0 * sc0 + rs0;  l1 = l1 * sc1 + rs1;
        m0 = nm0;  m1 = nm1;
#pragma unroll
        for (int nt = 0; nt < 8; nt++) {
            o[nt][0] *= sc0; o[nt][1] *= sc0;
            o[nt][2] *= sc1; o[nt][3] *= sc1;
        }

        // ---- O += P V  (P A-frags straight from S C-frags)
#pragma unroll
        for (int ks = 0; ks < 8; ks++) {
            uint32_t ah[4];
            ah[0] = packh2(s[2 * ks][0],     s[2 * ks][1]);
            ah[1] = packh2(s[2 * ks][2],     s[2 * ks][3]);
            ah[2] = packh2(s[2 * ks + 1][0], s[2 * ks + 1][1]);
            ah[3] = packh2(s[2 * ks + 1][2], s[2 * ks + 1][3]);
#pragma unroll
            for (int nt = 0; nt < 8; nt++) {
                uint32_t vh_[2];
                *(uint2*)vh_ = *(const uint2*)&sm[4096 + (ks * 8 + nt) * 64 + lane * 2];
                mma_f16(o[nt], ah, vh_);
            }
        }
    }

    // ---- normalize + store ctx tile (row-major (MTOT, 512), col h*64+d)
    float i0v = 1.f / l0, i1v = 1.f / l1;
    float* cr0 = ctx + ((size_t)b * SS + row0) * 512 + h * 64;
    float* cr1 = cr0 + (size_t)8 * 512;
#pragma unroll
    for (int nt = 0; nt < 8; nt++) {
        float2 a = {o[nt][0] * i0v, o[nt][1] * i0v};
        float2 c2 = {o[nt][2] * i1v, o[nt][3] * i1v};
        *(float2*)(cr0 + nt * 8 + 2 * t) = a;
        *(float2*)(cr1 + nt * 8 + 2 * t) = c2;
    }
}

// ---------------- weight concat: 7 x (512,1024) -> g_wcat (3584,1024) ----------------
__global__ void copy_wcat_k(const float* __restrict__ w0, const float* __restrict__ w1,
                            const float* __restrict__ w2, const float* __restrict__ w3,
                            const float* __restrict__ w4, const float* __restrict__ w5,
                            const float* __restrict__ w6, float* __restrict__ dst)
{
    size_t idx = (size_t)blockIdx.x * blockDim.x + threadIdx.x;
    const size_t per = (size_t)512 * DM;
    if (idx >= 7 * per) return;
    int p = (int)(idx / per);
    size_t off = idx % per;
    const float* w = w0;
    if (p == 1) w = w1; else if (p == 2) w = w2; else if (p == 3) w = w3;
    else if (p == 4) w = w4; else if (p == 5) w = w5; else if (p == 6) w = w6;
    dst[idx] = w[off];
}

// ---------------- RoPE on slabs {0:q_sa, 1:k_sa, 3:qa, 4:ka} of g_proj ----------------
__global__ void rope_k(float* __restrict__ proj, const float* __restrict__ fc,
                       const float* __restrict__ fs)
{
    size_t idx = (size_t)blockIdx.x * blockDim.x + threadIdx.x;
    int m = idx & 31;
    int h = (idx >> 5) & 7;
    int p = (idx >> 8) & 3;
    size_t row = idx >> 10;
    if (row >= (size_t)MTOT) return;
    int s = (int)(row & (SS - 1));
    int pc = (p < 2) ? p : p + 1;     // {0,1,3,4}
    float* base = proj + row * PLD + pc * 512 + h * 64 + 2 * m;
    float c = fc[s * 32 + m];
    float sn = fs[s * 32 + m];
    float xr = base[0], xi = base[1];
    base[0] = xr * c - xi * sn;
    base[1] = xr * sn + xi * c;
}

// ---------------- causal band softmax: reads and writes only j < band end ----------------
__global__ void softmax_k(float* __restrict__ sc)
{
    int i = blockIdx.x;
    long long g = blockIdx.y;
    float* row = sc + (g * SS + (long long)i) * SS;
    int t = threadIdx.x;
    int wlim = ((i >> 7) + 1) << 7;       // causal band end (multiple of 128)
    const int C = SS / 256;
    float vals[C];
    float mx = -3.4e38f;
#pragma unroll
    for (int c = 0; c < C; c++) {
        int j = t + c * 256;
        float v = -3.4e38f;
        if (j < wlim && j <= i) v = row[j];
        vals[c] = v;
        mx = fmaxf(mx, v);
    }
    __shared__ float red[256];
    red[t] = mx; __syncthreads();
    for (int o = 128; o > 0; o >>= 1) { if (t < o) red[t] = fmaxf(red[t], red[t + o]); __syncthreads(); }
    mx = red[0];
    __syncthreads();
    float sum = 0.f;
#pragma unroll
    for (int c = 0; c < C; c++) {
        float e = __expf(vals[c] - mx);
        vals[c] = e;
        sum += e;
    }
    red[t] = sum; __syncthreads();
    for (int o = 128; o > 0; o >>= 1) { if (t < o) red[t] += red[t + o]; __syncthreads(); }
    float inv = 1.0f / red[0];
#pragma unroll
    for (int c = 0; c < C; c++) {
        int j = t + c * 256;
        if (j < wlim) row[j] = vals[c] * inv;
    }
}

// ---------------- attended_rel v2: coalesced, smem-staged ----------------
__global__ void attrel_k2(const float* __restrict__ alpha, const float* __restrict__ rel,
                          float* __restrict__ out)
{
    int i = blockIdx.x, b = blockIdx.y;
    int t = threadIdx.x;
    __shared__ float sA[8][256], sR[8][256];
    __shared__ float red[256];
    int o = t & 63, sl = t >> 6;          // o = h*8+r, slice 0..3
    int h = o >> 3, r = o & 7;
    float acc = 0.f;
    for (int j0 = 0; j0 <= i; j0 += 256) {
        __syncthreads();
        for (int k = t; k < 2048; k += 256) {
            int row = k >> 8, col = k & 255;
            int j = j0 + col;
            float av = 0.f, rv = 0.f;
            if (j <= i) {
                av = alpha[((size_t)(b * 8 + row) * SS + i) * SS + j];
                rv = rel[((size_t)(b * 8 + row) * SS + i) * SS + j];
            }
            sA[row][col] = av;
            sR[row][col] = rv;
        }
        __syncthreads();
        const float* pa = &sA[h][sl * 64];
        const float* pr = &sR[r][sl * 64];
#pragma unroll 8
        for (int c = 0; c < 64; c++) acc += pa[c] * pr[c];
    }
    red[t] = acc;
    __syncthreads();
    if (t < 64)
        out[((size_t)b * SS + i) * 64 + t] = red[t] + red[t + 64] + red[t + 128] + red[t + 192];
}

// ---------------- ctx_ra += einsum('bihr,hdr->bihd', attrel, wr) ----------------
__global__ void relout_k(const float* __restrict__ attrel, const float* __restrict__ wr,
                         float* __restrict__ ctx)
{
    size_t idx = (size_t)blockIdx.x * blockDim.x + threadIdx.x;
    if (idx >= (size_t)MTOT * 512) return;
    int d = idx & 63;
    int h = (idx >> 6) & 7;
    size_t bi = idx >> 9;
    const float* ar = attrel + bi * 64 + h * 8;
    const float* w = wr + ((size_t)h * 64 + d) * 8;
    float v = 0.f;
#pragma unroll
    for (int r = 0; r < 8; r++) v += ar[r] * w[r];
    ctx[idx] += v;
}

// ---------------- launcher (multi-stream fork/join, graph-capture safe) ----------------
extern "C" void kernel_launch(void* const* d_in, const int* in_sizes, int n_in,
                              void* d_out, int out_size)
{
    const float* x     = (const float*)d_in[0];
    const float* symb  = (const float*)d_in[1];
    const float* fc    = (const float*)d_in[2];
    const float* fs    = (const float*)d_in[3];
    const float* wq_sa = (const float*)d_in[4];
    const float* wk_sa = (const float*)d_in[5];
    const float* wv_sa = (const float*)d_in[6];
    const float* wo_sa = (const float*)d_in[7];
    const float* wq_at = (const float*)d_in[8];
    const float* wk_at = (const float*)d_in[9];
    const float* wq_rl = (const float*)d_in[10];
    const float* wk_rl = (const float*)d_in[11];
    const float* wr    = (const float*)d_in[12];
    const float* wv_ra = (const float*)d_in[13];
    const float* wo_ra = (const float*)d_in[14];
    float* out = (float*)d_out;

    float *wcat, *proj, *sv, *sc_ra, *rel, *ctx_sa, *ctx_ra, *attrel;
    cudaGetSymbolAddress((void**)&wcat,   g_wcat);
    cudaGetSymbolAddress((void**)&proj,   g_proj);
    cudaGetSymbolAddress((void**)&sv,     g_sv);
    cudaGetSymbolAddress((void**)&sc_ra,  g_sc_ra);
    cudaGetSymbolAddress((void**)&rel,    g_rel);
    cudaGetSymbolAddress((void**)&ctx_sa, g_ctx_sa);
    cudaGetSymbolAddress((void**)&ctx_ra, g_ctx_ra);
    cudaGetSymbolAddress((void**)&attrel, g_attrel);

    // streams/events created once, on the first (non-captured) correctness call
    static cudaStream_t s1 = nullptr, s2 = nullptr;
    static cudaEvent_t ev0, ev1, ev2, ev3, ev4;
    if (s1 == nullptr) {
        cudaStreamCreateWithFlags(&s1, cudaStreamNonBlocking);
        cudaStreamCreateWithFlags(&s2, cudaStreamNonBlocking);
        cudaEventCreateWithFlags(&ev0, cudaEventDisableTiming);
        cudaEventCreateWithFlags(&ev1, cudaEventDisableTiming);
        cudaEventCreateWithFlags(&ev2, cudaEventDisableTiming);
        cudaEventCreateWithFlags(&ev3, cudaEventDisableTiming);
        cudaEventCreateWithFlags(&ev4, cudaEventDisableTiming);
    }

    dim3 tpb(256);
    const float scl = 0.125f;                       // 1/sqrt(64)
    const long long bS  = (long long)SS * PLD;      // per-batch stride in proj
    const long long sHS = (long long)SS * SS;       // per-head score stride
    const long long sBS = (long long)HH * SS * SS;  // per-batch score stride

    // ---- fork
    cudaEventRecord(ev0, 0);
    cudaStreamWaitEvent(s1, ev0, 0);
    cudaStreamWaitEvent(s2, ev0, 0);

    // s1: sv = symbols @ wv_ra^T  (independent of x path)
    gemm_f16<128, true, false, false><<<dim3(4, 32, 1), tpb, 0, s1>>>(
        symb, DM, 0, 0, wv_ra, DM, 0, 0, sv, 512, 0, 0, MTOT, 512, DM, 1, 1.0f);

    // stream 0: fused input projections + RoPE
    copy_wcat_k<<<14336, 256>>>(wq_sa, wk_sa, wv_sa, wq_at, wk_at, wq_rl, wk_rl, wcat);
    gemm_f16<128, true, false, false><<<dim3(28, 32, 1), tpb>>>(
        x, DM, 0, 0, wcat, DM, 0, 0, proj, PLD, 0, 0, MTOT, PLD, DM, 1, 1.0f);
    rope_k<<<16384, 256>>>(proj, fc, fs);
    cudaEventRecord(ev1, 0);
    cudaStreamWaitEvent(s1, ev1, 0);
    cudaStreamWaitEvent(s2, ev1, 0);

    // stream 0: SA fused flash attention -> ctx_sa, then SA output projection
    flash_sa<<<dim3(16, 16), tpb>>>(proj, ctx_sa);
    gemm_f16<128, true, false, false><<<dim3(4, 32, 1), tpb>>>(
        ctx_sa, 512, 0, 0, wo_sa, 512, 0, 0, out, DM, 0, 0, MTOT, 512, 512, 1, 1.0f);

    // s1: RA scores -> band softmax -> alpha @ sv
    gemm_f16<128, true, true, false><<<dim3(16, 16, 16), tpb, 0, s1>>>(
        proj + 3 * 512, PLD, bS, 64, proj + 4 * 512, PLD, bS, 64,
        sc_ra, SS, sBS, sHS, SS, SS, 64, HH, scl);
    softmax_k<<<dim3(SS, BB * HH), 256, 0, s1>>>(sc_ra);
    cudaEventRecord(ev2, s1);                       // alpha_ra ready
    gemm_f16<64, false, false, true><<<dim3(1, 16, 16), tpb, 0, s1>>>(
        sc_ra, SS, sBS, sHS, sv, 512, (long long)SS * 512, 64,
        ctx_ra, 512, (long long)SS * 512, 64, SS, 64, SS, HH, 1.0f);
    cudaEventRecord(ev3, s1);                       // ctx_ra ready

    // s2: rel GEMM; attrel (needs rel + alpha_ra); relout (needs ctx_ra); RA out proj
    gemm_f16<128, true, true, false><<<dim3(16, 16, 16), tpb, 0, s2>>>(
        proj + 5 * 512, PLD, bS, 64, proj + 6 * 512, PLD, bS, 64,
        rel, SS, (long long)NREL * SS * SS, sHS, SS, SS, 64, NREL, scl);
    cudaStreamWaitEvent(s2, ev2, 0);
    attrel_k2<<<dim3(SS, BB), 256, 0, s2>>>(sc_ra, rel, attrel);
    cudaStreamWaitEvent(s2, ev3, 0);
    relout_k<<<8192, 256, 0, s2>>>(attrel, wr, ctx_ra);
    gemm_f16<128, true, false, false><<<dim3(4, 32, 1), tpb, 0, s2>>>(
        ctx_ra, 512, 0, 0, wo_ra, 512, 0, 0, out + 512, DM, 0, 0, MTOT, 512, 512, 1, 1.0f);

    // ---- join
    cudaEventRecord(ev4, s2);
    cudaStreamWaitEvent(0, ev4, 0);
}